// round 3
// baseline (speedup 1.0000x reference)
#include <cuda_runtime.h>
#include <math.h>

#define NB 16
#define NC 256
#define NN 4096
#define NK 8
#define HALF_OUT (NB*NC*NN)

// ---------------- device scratch (no allocations allowed) ----------------
__device__ float  d_gate  [2*NB*NN];
__device__ float  d_assign[2*NB*NK*NN];
__device__ float  d_ag    [2*NB*NK*NN];
__device__ float  d_s     [2*NB*NK];
__device__ float  d_S2    [2*NB*NK*NK];
__device__ float  d_wx    [2*NB*NK*NC];
__device__ float  d_gflat [2*NB*NK*NC];
__device__ float  d_y4    [4*NB*NC*NK];
__device__ float  d_ce    [2*NB*NC*NK];
__device__ float2 d_pre   [2*NK*NC];
__device__ float  d_ck    [2*NK];
__device__ float  d_cwT   [2*NC*NC];
__device__ float  d_mpart [2*NB*NC];
__device__ float  d_vpart [2*NB*NC];
__device__ float  d_alpha [2*NC];
__device__ float  d_beta  [2*NC];

// ---------------- helpers ----------------
__device__ __forceinline__ float sigmoidf_(float x){ return 1.f/(1.f+expf(-x)); }

__device__ __forceinline__ float warpSum(float v){
  #pragma unroll
  for(int o=16;o>0;o>>=1) v += __shfl_xor_sync(0xffffffffu, v, o);
  return v;
}
// block-wide sum, blockDim.x multiple of 32, <=256; result broadcast to all
__device__ float blockSum(float v, float* scratch){
  int lane = threadIdx.x & 31, w = threadIdx.x >> 5;
  int nw = blockDim.x >> 5;
  v = warpSum(v);
  if(lane==0) scratch[w]=v;
  __syncthreads();
  float r = (threadIdx.x < nw) ? scratch[threadIdx.x] : 0.f;
  if(w==0) r = warpSum(r);
  if(threadIdx.x==0) scratch[0]=r;
  __syncthreads();
  r = scratch[0];
  __syncthreads();
  return r;
}

// ---------------- kP: per-side anchor coefficients ----------------
__global__ void kP(const float* rgb_anchor, const float* rgb_sigma,
                   const float* t_anchor,  const float* t_sigma){
  int s = blockIdx.y, k = blockIdx.x, t = threadIdx.x;
  const float* anc = s ? t_anchor : rgb_anchor;
  const float* sig = s ? t_sigma  : rgb_sigma;
  float sg  = sigmoidf_(sig[k*NC+t]);
  float is2 = 1.f/(sg*sg);
  float a   = anc[k*NC+t];
  d_pre[(s*NK+k)*NC+t] = make_float2(is2, 2.f*a*is2);
  __shared__ float sc[8];
  float ck = blockSum(a*a*is2, sc);
  if(t==0) d_ck[s*NK+k] = ck;
}

// ---------------- kT: transpose mutual-conv weights ----------------
__global__ void kT(const float* t2r_w, const float* r2t_w){
  int s = blockIdx.y, o = blockIdx.x, i = threadIdx.x;
  const float* w = s ? r2t_w : t2r_w;
  d_cwT[(size_t)s*NC*NC + i*NC + o] = w[o*NC + i];   // read coalesced
}

// ---------------- kB: gate + q-distances + softmax assignment ----------------
__global__ void __launch_bounds__(256) kB(const float* rgb, const float* tt,
      const float* edger, const float* edget, const float* pred_w, const float* pred_b){
  int chunk = blockIdx.x, b = blockIdx.y, s = blockIdx.z;
  int t = threadIdx.x;
  __shared__ float  pw[NC];
  __shared__ float2 pre[NK*NC];
  pw[t] = pred_w[t];
  for(int i=t;i<NK*NC;i+=256) pre[i] = d_pre[s*NK*NC + i];
  __syncthreads();
  int n = chunk*256 + t;
  const float* ep = (s ? edget : edger) + (size_t)b*NC*NN;
  const float* xp = (s ? tt    : rgb  ) + (size_t)b*NC*NN;
  float ga = 0.f;
  for(int c=0;c<NC;c++) ga += pw[c]*ep[(size_t)c*NN + n];
  float g = sigmoidf_(ga + pred_b[0]);
  float q[NK];
  #pragma unroll
  for(int k=0;k<NK;k++) q[k] = d_ck[s*NK+k];
  for(int c=0;c<NC;c++){
    float xv  = xp[(size_t)c*NN+n]*g;
    float xv2 = xv*xv;
    #pragma unroll
    for(int k=0;k<NK;k++){
      float2 pc = pre[k*NC+c];
      q[k] += xv2*pc.x - xv*pc.y;
    }
  }
  float mx = -0.5f*q[0];
  #pragma unroll
  for(int k=1;k<NK;k++) mx = fmaxf(mx, -0.5f*q[k]);
  float a[NK]; float ssum=0.f;
  #pragma unroll
  for(int k=0;k<NK;k++){ a[k] = expf(-0.5f*q[k]-mx); ssum += a[k]; }
  float inv = 1.f/ssum;
  float* asp = d_assign + (size_t)(s*NB+b)*NK*NN;
  float* agp = d_ag     + (size_t)(s*NB+b)*NK*NN;
  #pragma unroll
  for(int k=0;k<NK;k++){
    float av = a[k]*inv;
    asp[(size_t)k*NN+n] = av;
    agp[(size_t)k*NN+n] = av*g;
  }
  d_gate[(s*NB+b)*NN + n] = g;
}

// ---------------- kC: wx[s,b,k,c] = sum_n (assign*gate)[k,n] * x[c,n] ----------------
__global__ void __launch_bounds__(256) kC(const float* rgb, const float* tt){
  int cg = blockIdx.x, b = blockIdx.y, s = blockIdx.z;
  int t = threadIdx.x;
  int cl = t >> 3, nsub = t & 7;
  int c = cg*32 + cl;
  __shared__ float ags[NK][1024];
  __shared__ float red[32][NK][9];
  const float* xp  = (s ? tt : rgb) + ((size_t)b*NC + c)*NN;
  const float* agp = d_ag + (size_t)(s*NB+b)*NK*NN;
  float acc[NK];
  #pragma unroll
  for(int k=0;k<NK;k++) acc[k]=0.f;
  for(int t0=0;t0<NN;t0+=1024){
    for(int i=t;i<NK*1024;i+=256){
      int k=i>>10, nn=i&1023;
      ags[k][nn] = agp[(size_t)k*NN + t0 + nn];
    }
    __syncthreads();
    for(int i=0;i<128;i++){
      int nn = nsub + i*8;
      float xv = xp[t0+nn];
      #pragma unroll
      for(int k=0;k<NK;k++) acc[k] += ags[k][nn]*xv;
    }
    __syncthreads();
  }
  #pragma unroll
  for(int k=0;k<NK;k++) red[cl][nsub][k] = acc[k];
  __syncthreads();
  int cl2 = t>>3, k2 = t&7;
  float sum = 0.f;
  #pragma unroll
  for(int p=0;p<8;p++) sum += red[cl2][p][k2];
  d_wx[((size_t)(s*NB+b)*NK + k2)*NC + cg*32 + cl2] = sum;
}

// ---------------- kC2: s[b,k] and S2[b,k,l] from assign ----------------
__global__ void kC2(){
  int p = blockIdx.x, b = blockIdx.y, s = blockIdx.z;
  int k=0, pp=p;
  while(pp >= NK-k){ pp -= NK-k; k++; }
  int l = k+pp;
  const float* ak = d_assign + ((size_t)(s*NB+b)*NK + k)*NN;
  const float* al = d_assign + ((size_t)(s*NB+b)*NK + l)*NN;
  int t = threadIdx.x;
  float a1=0.f, a2=0.f;
  for(int n=t;n<NN;n+=256){ float va = ak[n]; a1 += va*al[n]; a2 += va; }
  __shared__ float sc[8];
  float S  = blockSum(a1, sc);
  float Sk = blockSum(a2, sc);
  if(t==0){
    d_S2[(s*NB+b)*64 + k*8 + l] = S;
    d_S2[(s*NB+b)*64 + l*8 + k] = S;
    if(k==l) d_s[(s*NB+b)*8 + k] = Sk;
  }
}

// ---------------- kD: nodes -> per-k l2norm -> global l2norm -> gflat ----------------
__global__ void kD(const float* rgb_anchor, const float* rgb_sigma,
                   const float* t_anchor,  const float* t_sigma){
  int b = blockIdx.x, s = blockIdx.y, t = threadIdx.x;
  __shared__ float v[NK][NC];
  __shared__ float sc[8];
  const float* anc = s ? t_anchor : rgb_anchor;
  const float* sig = s ? t_sigma  : rgb_sigma;
  const float* wxp = d_wx + (size_t)(s*NB+b)*NK*NC;
  const float* sbp = d_s  + (s*NB+b)*NK;
  float nk[NK];
  for(int k=0;k<NK;k++){
    float sv  = sbp[k];
    float sg  = sigmoidf_(sig[k*NC+t]);
    float val = (wxp[k*NC+t] - sv*anc[k*NC+t]) / sg / (sv + 1e-9f);
    v[k][t] = val;
    float ss = blockSum(val*val, sc);
    nk[k] = fmaxf(sqrtf(ss), 1e-12f);
  }
  float gss = 0.f;
  for(int k=0;k<NK;k++){ float nv = v[k][t]/nk[k]; v[k][t]=nv; gss += nv*nv; }
  float G = blockSum(gss, sc);
  float gn = fmaxf(sqrtf(G), 1e-12f);
  float* gf = d_gflat + (size_t)(s*NB+b)*2048;
  for(int k=0;k<NK;k++) gf[k*NC+t] = v[k][t]/gn;
}

// ---------------- kE: 4 graph convs + training-mode BN(relu) over (B,K) ----------------
__global__ void __launch_bounds__(128) kE(
    const float* w0,const float* g0,const float* b0,
    const float* w1,const float* g1,const float* b1,
    const float* w2,const float* g2,const float* b2,
    const float* w3,const float* g3,const float* b3){
  int o = blockIdx.x, conv = blockIdx.y, t = threadIdx.x;
  const float *W, *gg, *bb;
  if(conv==0){W=w0;gg=g0;bb=b0;} else if(conv==1){W=w1;gg=g1;bb=b1;}
  else if(conv==2){W=w2;gg=g2;bb=b2;} else {W=w3;gg=g3;bb=b3;}
  int side = conv>>1;
  __shared__ float wr[NC];
  __shared__ float sc[8];
  wr[t] = W[o*NC + t]; wr[t+128] = W[o*NC + t + 128];
  __syncthreads();
  int b = t >> 3, k = t & 7;
  const float* gf = d_gflat + (size_t)(side*NB+b)*2048;
  float acc = 0.f;
  for(int i=0;i<NC;i++) acc += wr[i]*gf[i*8+k];     // graph[b,i,k] = gflat[i*8+k]
  float su = blockSum(acc, sc);
  float sq = blockSum(acc*acc, sc);
  float mean = su*(1.f/128.f);
  float var  = sq*(1.f/128.f) - mean*mean;
  float y = gg[o]*(acc-mean)*rsqrtf(var+1e-5f) + bb[o];
  d_y4[((size_t)(conv*NB+b)*NC + o)*NK + k] = fmaxf(y, 0.f);
}

// ---------------- kF: mutual correlation + 2x cascade GCN + conv fold + BN stats ----------------
__global__ void __launch_bounds__(256) kF(
    const float* t2r_g1, const float* t2r_g2, const float* r2t_g1, const float* r2t_g2){
  int b = blockIdx.x, s = blockIdx.y, t = threadIdx.x;
  const float* W1  = s ? r2t_g1 : t2r_g1;
  const float* W2  = s ? r2t_g2 : t2r_g2;
  const float* cwT = d_cwT + (size_t)s*NC*NC;
  int c1 = s ? 0 : 2;  // r1/r2 conv indices (t2r uses t_g1/t_g2 = convs 2,3)
  __shared__ float e[NC][NK], r1[NC][NK], r2[NC][NK], xa[NC][NK], xb[NC][NK];
  __shared__ float A[NK][NK+1];
  {
    const float* gf = d_gflat + (size_t)(s*NB+b)*2048;
    const float* y1 = d_y4 + (size_t)(c1*NB+b)*NC*NK;
    const float* y2 = d_y4 + (size_t)((c1+1)*NB+b)*NC*NK;
    #pragma unroll
    for(int k=0;k<NK;k++){
      e [t][k] = gf[t*NK+k];   // edge[c,k] = gflat[c*8+k]
      r1[t][k] = y1[t*NK+k];
      r2[t][k] = y2[t*NK+k];
    }
  }
  __syncthreads();
  // A[k,l] = softmax_l( sum_c e[c,k]*r1[c,l] )
  {
    int pair = t>>2, part = t&3;
    int k = pair>>3, l = pair&7;
    float acc=0.f;
    for(int c=part;c<NC;c+=4) acc += e[c][k]*r1[c][l];
    acc += __shfl_down_sync(0xffffffffu, acc, 1);
    acc += __shfl_down_sync(0xffffffffu, acc, 2);
    if(part==0) A[k][l] = acc;
  }
  __syncthreads();
  if(t<NK){
    float mx=A[t][0];
    #pragma unroll
    for(int l=1;l<NK;l++) mx = fmaxf(mx, A[t][l]);
    float sm=0.f, ee[NK];
    #pragma unroll
    for(int l=0;l<NK;l++){ ee[l]=expf(A[t][l]-mx); sm+=ee[l]; }
    #pragma unroll
    for(int l=0;l<NK;l++) A[t][l] = ee[l]/sm;
  }
  __syncthreads();
  // x0 = e + A . r2
  {
    float rr[NK];
    #pragma unroll
    for(int l=0;l<NK;l++) rr[l]=r2[t][l];
    #pragma unroll
    for(int k=0;k<NK;k++){
      float m=0.f;
      #pragma unroll
      for(int l=0;l<NK;l++) m += A[k][l]*rr[l];
      xa[t][k] = e[t][k] + m;
    }
  }
  __syncthreads();
  // cascade GCN, 2 iterations; relu only at the end
  for(int it=0; it<2; it++){
    float (*xin)[NK]  = it ? xb : xa;
    float (*xout)[NK] = it ? xa : xb;
    const float* W = it ? W2 : W1;
    {
      int pair=t>>2, part=t&3, k=pair>>3, l=pair&7;
      float acc=0.f;
      for(int c=part;c<NC;c+=4) acc += xin[c][k]*xin[c][l];
      acc += __shfl_down_sync(0xffffffffu, acc, 1);
      acc += __shfl_down_sync(0xffffffffu, acc, 2);
      if(part==0) A[k][l]=acc;
    }
    __syncthreads();
    if(t<NK){
      float mx=A[t][0];
      #pragma unroll
      for(int l=1;l<NK;l++) mx=fmaxf(mx,A[t][l]);
      float sm=0.f, ee[NK];
      #pragma unroll
      for(int l=0;l<NK;l++){ ee[l]=expf(A[t][l]-mx); sm+=ee[l]; }
      #pragma unroll
      for(int l=0;l<NK;l++) A[t][l]=ee[l]/sm;
    }
    __syncthreads();
    float acc[NK];
    #pragma unroll
    for(int l=0;l<NK;l++) acc[l]=0.f;
    for(int i=0;i<NC;i++){
      float w = W[i*NC + t];              // coalesced column read
      #pragma unroll
      for(int l=0;l<NK;l++) acc[l] += xin[i][l]*w;
    }
    bool last = (it==1);
    #pragma unroll
    for(int k=0;k<NK;k++){
      float v=0.f;
      #pragma unroll
      for(int l=0;l<NK;l++) v += A[k][l]*acc[l];
      xout[t][k] = last ? fmaxf(v,0.f) : v;
    }
    __syncthreads();
  }
  // ce[o,k] = sum_i cw[o,i]*edge2[i,k]  (cwT pre-transposed)
  float ce[NK];
  #pragma unroll
  for(int k=0;k<NK;k++) ce[k]=0.f;
  for(int i=0;i<NC;i++){
    float w = cwT[i*NC + t];
    #pragma unroll
    for(int k=0;k<NK;k++) ce[k] += xa[i][k]*w;
  }
  const float* sb = d_s  + (s*NB+b)*NK;
  const float* S2 = d_S2 + (s*NB+b)*64;
  float mp=0.f, vp=0.f;
  #pragma unroll
  for(int k=0;k<NK;k++) mp += ce[k]*sb[k];
  #pragma unroll
  for(int k=0;k<NK;k++)
    #pragma unroll
    for(int l=0;l<NK;l++) vp += ce[k]*ce[l]*S2[k*8+l];
  d_mpart[(s*NB+b)*NC + t] = mp;
  d_vpart[(s*NB+b)*NC + t] = vp;
  float* cep = d_ce + ((size_t)(s*NB+b)*NC + t)*NK;
  #pragma unroll
  for(int k=0;k<NK;k++) cep[k] = ce[k];
}

// ---------------- kG: fold BN stats into alpha/beta ----------------
__global__ void kG(const float* t2r_g, const float* t2r_b,
                   const float* r2t_g, const float* r2t_b){
  int s = blockIdx.x, t = threadIdx.x;
  const float* gg = s ? r2t_g : t2r_g;
  const float* bb = s ? r2t_b : t2r_b;
  float ms=0.f, vs=0.f;
  for(int b=0;b<NB;b++){ ms += d_mpart[(s*NB+b)*NC+t]; vs += d_vpart[(s*NB+b)*NC+t]; }
  float mean = ms * (1.f/65536.f);
  float ey2  = vs * (1.f/65536.f);
  float var  = ey2 - mean*mean;
  float al = gg[t]*rsqrtf(var + 1e-5f);
  d_alpha[s*NC+t] = al;
  d_beta [s*NC+t] = bb[t] - al*mean;
}

// ---------------- kH: out = gate*x + relu(alpha*(ce.assign) + beta) ----------------
__global__ void __launch_bounds__(256) kH(const float* rgb, const float* tt, float* out){
  int chunk = blockIdx.x, b = blockIdx.y;
  int s = blockIdx.z >> 1, ch = blockIdx.z & 1;
  int t = threadIdx.x;
  __shared__ float as_[NK][256];
  __shared__ float ces[128][NK];
  __shared__ float al[128], be[128];
  int n0 = chunk*256;
  const float* asp = d_assign + (size_t)(s*NB+b)*NK*NN;
  #pragma unroll
  for(int k=0;k<NK;k++) as_[k][t] = asp[(size_t)k*NN + n0 + t];
  float g = d_gate[(s*NB+b)*NN + n0 + t];
  const float* cep = d_ce + ((size_t)(s*NB+b)*NC + ch*128)*NK;
  for(int i=t;i<128*NK;i+=256) ((float*)ces)[i] = cep[i];
  if(t<128){ al[t]=d_alpha[s*NC+ch*128+t]; be[t]=d_beta[s*NC+ch*128+t]; }
  __syncthreads();
  float av[NK];
  #pragma unroll
  for(int k=0;k<NK;k++) av[k]=as_[k][t];
  const float* xp = (s ? tt : rgb) + (size_t)b*NC*NN;
  float* op = out + (size_t)s*HALF_OUT + (size_t)b*NC*NN;
  for(int cl=0; cl<128; cl++){
    int c = ch*128 + cl;
    float xv = xp[(size_t)c*NN + n0 + t];
    float p = 0.f;
    #pragma unroll
    for(int k=0;k<NK;k++) p += ces[cl][k]*av[k];
    op[(size_t)c*NN + n0 + t] = g*xv + fmaxf(al[cl]*p + be[cl], 0.f);
  }
}

// ---------------- launch ----------------
extern "C" void kernel_launch(void* const* d_in, const int* in_sizes, int n_in,
                              void* d_out, int out_size){
  (void)in_sizes; (void)n_in; (void)out_size;
  const float* rgb    = (const float*)d_in[0];
  const float* tt     = (const float*)d_in[1];
  const float* edger  = (const float*)d_in[2];
  const float* edget  = (const float*)d_in[3];
  const float* pred_w = (const float*)d_in[4];
  const float* pred_b = (const float*)d_in[5];
  const float* rgb_anchor=(const float*)d_in[6];
  const float* rgb_sigma =(const float*)d_in[7];
  const float* t_anchor  =(const float*)d_in[8];
  const float* t_sigma   =(const float*)d_in[9];
  const float* rgb_c1_w=(const float*)d_in[10]; const float* rgb_c1_g=(const float*)d_in[11]; const float* rgb_c1_b=(const float*)d_in[12];
  const float* rgb_c2_w=(const float*)d_in[13]; const float* rgb_c2_g=(const float*)d_in[14]; const float* rgb_c2_b=(const float*)d_in[15];
  const float* t_c1_w  =(const float*)d_in[16]; const float* t_c1_g  =(const float*)d_in[17]; const float* t_c1_b  =(const float*)d_in[18];
  const float* t_c2_w  =(const float*)d_in[19]; const float* t_c2_g  =(const float*)d_in[20]; const float* t_c2_b  =(const float*)d_in[21];
  const float* t2r_conv_w=(const float*)d_in[22]; const float* t2r_conv_g=(const float*)d_in[23]; const float* t2r_conv_b=(const float*)d_in[24];
  const float* r2t_conv_w=(const float*)d_in[25]; const float* r2t_conv_g=(const float*)d_in[26]; const float* r2t_conv_b=(const float*)d_in[27];
  const float* t2r_g1=(const float*)d_in[28]; const float* t2r_g2=(const float*)d_in[29];
  const float* r2t_g1=(const float*)d_in[30]; const float* r2t_g2=(const float*)d_in[31];
  float* out = (float*)d_out;

  kP <<<dim3(NK,2), NC>>>(rgb_anchor, rgb_sigma, t_anchor, t_sigma);
  kT <<<dim3(NC,2), NC>>>(t2r_conv_w, r2t_conv_w);
  kB <<<dim3(16,NB,2), 256>>>(rgb, tt, edger, edget, pred_w, pred_b);
  kC <<<dim3(8,NB,2), 256>>>(rgb, tt);
  kC2<<<dim3(36,NB,2), 256>>>();
  kD <<<dim3(NB,2), NC>>>(rgb_anchor, rgb_sigma, t_anchor, t_sigma);
  kE <<<dim3(NC,4), 128>>>(rgb_c1_w,rgb_c1_g,rgb_c1_b, rgb_c2_w,rgb_c2_g,rgb_c2_b,
                           t_c1_w,t_c1_g,t_c1_b, t_c2_w,t_c2_g,t_c2_b);
  kF <<<dim3(NB,2), 256>>>(t2r_g1, t2r_g2, r2t_g1, r2t_g2);
  kG <<<2, NC>>>(t2r_conv_g, t2r_conv_b, r2t_conv_g, r2t_conv_b);
  kH <<<dim3(16,NB,4), 256>>>(rgb, tt, out);
}

// round 4
// speedup vs baseline: 1.1855x; 1.1855x over previous
#include <cuda_runtime.h>
#include <math.h>

#define NB 16
#define NC 256
#define NN 4096
#define NK 8
#define HALF_OUT (NB*NC*NN)

// ---------------- device scratch (no allocations allowed) ----------------
__device__ float  d_gate  [2*NB*NN];
__device__ float  d_ag    [2*NB*NK*NN];
__device__ float  d_s     [2*NB*NK];
__device__ float  d_S2    [2*NB*NK*NK];
__device__ float  d_wxp   [4*2*NB*NK*NC];     // per-nchunk partial wx
__device__ float  d_sS2p  [2*NB*16*44];       // per-chunk partial s/S2 from kB
__device__ float  d_gflat [2*NB*NK*NC];
__device__ float  d_y4    [4*NB*NC*NK];
__device__ float  d_ce    [2*NB*NC*NK];
__device__ float2 d_pre   [2*NK*NC];
__device__ float  d_ck    [2*NK];
__device__ float  d_cwT   [2*NC*NC];
__device__ float  d_mpart [2*NB*NC];
__device__ float  d_vpart [2*NB*NC];
__device__ float  d_alpha [2*NC];
__device__ float  d_beta  [2*NC];

// ---------------- helpers ----------------
__device__ __forceinline__ float sigmoidf_(float x){ return 1.f/(1.f+expf(-x)); }

__device__ __forceinline__ float warpSum(float v){
  #pragma unroll
  for(int o=16;o>0;o>>=1) v += __shfl_xor_sync(0xffffffffu, v, o);
  return v;
}
// block-wide sum, blockDim.x multiple of 32, <=256; result broadcast to all
__device__ float blockSum(float v, float* scratch){
  int lane = threadIdx.x & 31, w = threadIdx.x >> 5;
  int nw = blockDim.x >> 5;
  v = warpSum(v);
  if(lane==0) scratch[w]=v;
  __syncthreads();
  float r = (threadIdx.x < nw) ? scratch[threadIdx.x] : 0.f;
  if(w==0) r = warpSum(r);
  if(threadIdx.x==0) scratch[0]=r;
  __syncthreads();
  r = scratch[0];
  __syncthreads();
  return r;
}

// ---------------- kP: per-side anchor coefficients ----------------
__global__ void kP(const float* rgb_anchor, const float* rgb_sigma,
                   const float* t_anchor,  const float* t_sigma){
  int s = blockIdx.y, k = blockIdx.x, t = threadIdx.x;
  const float* anc = s ? t_anchor : rgb_anchor;
  const float* sig = s ? t_sigma  : rgb_sigma;
  float sg  = sigmoidf_(sig[k*NC+t]);
  float is2 = 1.f/(sg*sg);
  float a   = anc[k*NC+t];
  d_pre[(s*NK+k)*NC+t] = make_float2(is2, 2.f*a*is2);
  __shared__ float sc[8];
  float ck = blockSum(a*a*is2, sc);
  if(t==0) d_ck[s*NK+k] = ck;
}

// ---------------- kT: transpose mutual-conv weights ----------------
__global__ void kT(const float* t2r_w, const float* r2t_w){
  int s = blockIdx.y, o = blockIdx.x, i = threadIdx.x;
  const float* w = s ? r2t_w : t2r_w;
  d_cwT[(size_t)s*NC*NC + i*NC + o] = w[o*NC + i];   // read coalesced
}

// ---------------- kB: gate + q + softmax + per-block s/S2 partials ----------------
__global__ void __launch_bounds__(256) kB(const float* rgb, const float* tt,
      const float* edger, const float* edget, const float* pred_w, const float* pred_b){
  int chunk = blockIdx.x, b = blockIdx.y, s = blockIdx.z;
  int t = threadIdx.x;
  __shared__ float  pw[NC];
  __shared__ float2 pre[NK*NC];
  __shared__ float  part[44][8];
  pw[t] = pred_w[t];
  for(int i=t;i<NK*NC;i+=256) pre[i] = d_pre[s*NK*NC + i];
  __syncthreads();
  int n = chunk*256 + t;
  const float* ep = (s ? edget : edger) + (size_t)b*NC*NN;
  const float* xp = (s ? tt    : rgb  ) + (size_t)b*NC*NN;
  float ga0=0.f, ga1=0.f, ga2=0.f, ga3=0.f;
  #pragma unroll 2
  for(int c=0;c<NC;c+=4){
    ga0 += pw[c  ]*ep[(size_t)(c  )*NN + n];
    ga1 += pw[c+1]*ep[(size_t)(c+1)*NN + n];
    ga2 += pw[c+2]*ep[(size_t)(c+2)*NN + n];
    ga3 += pw[c+3]*ep[(size_t)(c+3)*NN + n];
  }
  float g = sigmoidf_((ga0+ga1)+(ga2+ga3) + pred_b[0]);
  float q[NK];
  #pragma unroll
  for(int k=0;k<NK;k++) q[k] = d_ck[s*NK+k];
  #pragma unroll 4
  for(int c=0;c<NC;c++){
    float xv  = xp[(size_t)c*NN+n]*g;
    float xv2 = xv*xv;
    #pragma unroll
    for(int k=0;k<NK;k++){
      float2 pc = pre[k*NC+c];
      q[k] += xv2*pc.x - xv*pc.y;
    }
  }
  float mx = -0.5f*q[0];
  #pragma unroll
  for(int k=1;k<NK;k++) mx = fmaxf(mx, -0.5f*q[k]);
  float av[NK]; float ssum=0.f;
  #pragma unroll
  for(int k=0;k<NK;k++){ av[k] = expf(-0.5f*q[k]-mx); ssum += av[k]; }
  float inv = 1.f/ssum;
  #pragma unroll
  for(int k=0;k<NK;k++) av[k] *= inv;
  float* agp = d_ag + (size_t)(s*NB+b)*NK*NN;
  #pragma unroll
  for(int k=0;k<NK;k++) agp[(size_t)k*NN+n] = av[k]*g;
  d_gate[(s*NB+b)*NN + n] = g;
  // s / S2 partial reductions (44 values): warp reduce -> smem -> 8-way sum
  int lane = t&31, w = t>>5;
  #pragma unroll
  for(int k=0;k<NK;k++){
    float v = warpSum(av[k]);
    if(lane==0) part[k][w]=v;
  }
  int idx=8;
  #pragma unroll
  for(int k=0;k<NK;k++)
    #pragma unroll
    for(int l=k;l<NK;l++){
      float v = warpSum(av[k]*av[l]);
      if(lane==0) part[idx][w]=v;
      idx++;
    }
  __syncthreads();
  if(t<44){
    float sv=0.f;
    #pragma unroll
    for(int p=0;p<8;p++) sv += part[t][p];
    d_sS2p[((s*NB+b)*16+chunk)*44 + t] = sv;
  }
}

// ---------------- kC: partial wx[k,c] = sum_{n in chunk} ag[k,n]*x[c,n] ----------------
__global__ void __launch_bounds__(256) kC(const float* rgb, const float* tt){
  int bx = blockIdx.x;                // 0..31: nchunk (4) x cgroup (8)
  int nch = bx>>3, cg = bx&7;
  int b = blockIdx.y, s = blockIdx.z;
  int t = threadIdx.x;
  int cl = t >> 3, nsub = t & 7;
  int c = cg*32 + cl;
  __shared__ float ags[NK][1024];
  __shared__ float red[32][NK][9];
  const float* agp = d_ag + (size_t)(s*NB+b)*NK*NN + nch*1024;
  for(int i=t;i<2048;i+=256){
    int k=i>>8, j=i&255;
    ((float4*)ags[k])[j] = ((const float4*)(agp + (size_t)k*NN))[j];
  }
  __syncthreads();
  const float4* xp4 = (const float4*)((s ? tt : rgb) + ((size_t)b*NC + c)*NN + nch*1024);
  float acc[NK];
  #pragma unroll
  for(int k=0;k<NK;k++) acc[k]=0.f;
  #pragma unroll 4
  for(int i=0;i<32;i++){
    int j = nsub + i*8;
    float4 xv = xp4[j];
    #pragma unroll
    for(int k=0;k<NK;k++){
      float4 a4 = ((float4*)ags[k])[j];
      acc[k] += a4.x*xv.x + a4.y*xv.y + a4.z*xv.z + a4.w*xv.w;
    }
  }
  #pragma unroll
  for(int k=0;k<NK;k++) red[cl][nsub][k] = acc[k];
  __syncthreads();
  int cl2 = t>>3, k2 = t&7;
  float sum = 0.f;
  #pragma unroll
  for(int p=0;p<8;p++) sum += red[cl2][p][k2];
  d_wxp[((size_t)(nch*(2*NB) + s*NB+b)*NK + k2)*NC + cg*32 + cl2] = sum;
}

// ---------------- kD: reduce partials, nodes -> l2norms -> gflat ----------------
__global__ void kD(const float* rgb_anchor, const float* rgb_sigma,
                   const float* t_anchor,  const float* t_sigma){
  int b = blockIdx.x, s = blockIdx.y, t = threadIdx.x;
  __shared__ float v[NK][NC];
  __shared__ float sc[8];
  __shared__ float s_sh[NK];
  // reduce s / S2 partials over 16 chunks
  if(t<44){
    float sv=0.f;
    for(int ch=0;ch<16;ch++) sv += d_sS2p[((s*NB+b)*16+ch)*44 + t];
    if(t<8){ d_s[(s*NB+b)*8 + t] = sv; s_sh[t] = sv; }
    else {
      int p=t-8, k=0;
      while(p >= NK-k){ p -= NK-k; k++; }
      int l = k+p;
      d_S2[(s*NB+b)*64 + k*8 + l] = sv;
      d_S2[(s*NB+b)*64 + l*8 + k] = sv;
    }
  }
  __syncthreads();
  const float* anc = s ? t_anchor : rgb_anchor;
  const float* sig = s ? t_sigma  : rgb_sigma;
  float nk[NK];
  for(int k=0;k<NK;k++){
    float wxv = 0.f;
    #pragma unroll
    for(int ch=0;ch<4;ch++)
      wxv += d_wxp[((size_t)(ch*(2*NB) + s*NB+b)*NK + k)*NC + t];
    float sv  = s_sh[k];
    float sg  = sigmoidf_(sig[k*NC+t]);
    float val = (wxv - sv*anc[k*NC+t]) / sg / (sv + 1e-9f);
    v[k][t] = val;
    float ss = blockSum(val*val, sc);
    nk[k] = fmaxf(sqrtf(ss), 1e-12f);
  }
  float gss = 0.f;
  for(int k=0;k<NK;k++){ float nv = v[k][t]/nk[k]; v[k][t]=nv; gss += nv*nv; }
  float G = blockSum(gss, sc);
  float gn = fmaxf(sqrtf(G), 1e-12f);
  float* gf = d_gflat + (size_t)(s*NB+b)*2048;
  for(int k=0;k<NK;k++) gf[k*NC+t] = v[k][t]/gn;
}

// ---------------- kE: 4 graph convs + training-mode BN(relu) over (B,K) ----------------
__global__ void __launch_bounds__(128) kE(
    const float* w0,const float* g0,const float* b0,
    const float* w1,const float* g1,const float* b1,
    const float* w2,const float* g2,const float* b2,
    const float* w3,const float* g3,const float* b3){
  int o = blockIdx.x, conv = blockIdx.y, t = threadIdx.x;
  const float *W, *gg, *bb;
  if(conv==0){W=w0;gg=g0;bb=b0;} else if(conv==1){W=w1;gg=g1;bb=b1;}
  else if(conv==2){W=w2;gg=g2;bb=b2;} else {W=w3;gg=g3;bb=b3;}
  int side = conv>>1;
  __shared__ float wr[NC];
  __shared__ float sc[8];
  wr[t] = W[o*NC + t]; wr[t+128] = W[o*NC + t + 128];
  __syncthreads();
  int b = t >> 3, k = t & 7;
  const float* gf = d_gflat + (size_t)(side*NB+b)*2048;
  float acc = 0.f;
  #pragma unroll 4
  for(int i=0;i<NC;i++) acc += wr[i]*gf[i*8+k];
  float su = blockSum(acc, sc);
  float sq = blockSum(acc*acc, sc);
  float mean = su*(1.f/128.f);
  float var  = sq*(1.f/128.f) - mean*mean;
  float y = gg[o]*(acc-mean)*rsqrtf(var+1e-5f) + bb[o];
  d_y4[((size_t)(conv*NB+b)*NC + o)*NK + k] = fmaxf(y, 0.f);
}

// ---------------- kF: mutual correlation + 2x cascade GCN + conv fold + BN stats ----------------
__global__ void __launch_bounds__(256) kF(
    const float* t2r_g1, const float* t2r_g2, const float* r2t_g1, const float* r2t_g2){
  int b = blockIdx.x, s = blockIdx.y, t = threadIdx.x;
  const float* W1  = s ? r2t_g1 : t2r_g1;
  const float* W2  = s ? r2t_g2 : t2r_g2;
  const float* cwT = d_cwT + (size_t)s*NC*NC;
  int c1 = s ? 0 : 2;  // t2r uses t_g1/t_g2 = convs 2,3; r2t uses rgb convs 0,1
  __shared__ float e[NC][NK], r1[NC][NK], r2[NC][NK], xa[NC][NK], xb[NC][NK];
  __shared__ float A[NK][NK+1];
  {
    const float* gf = d_gflat + (size_t)(s*NB+b)*2048;
    const float* y1 = d_y4 + (size_t)(c1*NB+b)*NC*NK;
    const float* y2 = d_y4 + (size_t)((c1+1)*NB+b)*NC*NK;
    #pragma unroll
    for(int k=0;k<NK;k++){
      e [t][k] = gf[t*NK+k];
      r1[t][k] = y1[t*NK+k];
      r2[t][k] = y2[t*NK+k];
    }
  }
  __syncthreads();
  {
    int pair = t>>2, part = t&3;
    int k = pair>>3, l = pair&7;
    float acc=0.f;
    #pragma unroll 4
    for(int c=part;c<NC;c+=4) acc += e[c][k]*r1[c][l];
    acc += __shfl_down_sync(0xffffffffu, acc, 1);
    acc += __shfl_down_sync(0xffffffffu, acc, 2);
    if(part==0) A[k][l] = acc;
  }
  __syncthreads();
  if(t<NK){
    float mx=A[t][0];
    #pragma unroll
    for(int l=1;l<NK;l++) mx = fmaxf(mx, A[t][l]);
    float sm=0.f, ee[NK];
    #pragma unroll
    for(int l=0;l<NK;l++){ ee[l]=expf(A[t][l]-mx); sm+=ee[l]; }
    #pragma unroll
    for(int l=0;l<NK;l++) A[t][l] = ee[l]/sm;
  }
  __syncthreads();
  {
    float rr[NK];
    #pragma unroll
    for(int l=0;l<NK;l++) rr[l]=r2[t][l];
    #pragma unroll
    for(int k=0;k<NK;k++){
      float m=0.f;
      #pragma unroll
      for(int l=0;l<NK;l++) m += A[k][l]*rr[l];
      xa[t][k] = e[t][k] + m;
    }
  }
  __syncthreads();
  for(int it=0; it<2; it++){
    float (*xin)[NK]  = it ? xb : xa;
    float (*xout)[NK] = it ? xa : xb;
    const float* W = it ? W2 : W1;
    {
      int pair=t>>2, part=t&3, k=pair>>3, l=pair&7;
      float acc=0.f;
      #pragma unroll 4
      for(int c=part;c<NC;c+=4) acc += xin[c][k]*xin[c][l];
      acc += __shfl_down_sync(0xffffffffu, acc, 1);
      acc += __shfl_down_sync(0xffffffffu, acc, 2);
      if(part==0) A[k][l]=acc;
    }
    __syncthreads();
    if(t<NK){
      float mx=A[t][0];
      #pragma unroll
      for(int l=1;l<NK;l++) mx=fmaxf(mx,A[t][l]);
      float sm=0.f, ee[NK];
      #pragma unroll
      for(int l=0;l<NK;l++){ ee[l]=expf(A[t][l]-mx); sm+=ee[l]; }
      #pragma unroll
      for(int l=0;l<NK;l++) A[t][l]=ee[l]/sm;
    }
    __syncthreads();
    float acc[NK];
    #pragma unroll
    for(int l=0;l<NK;l++) acc[l]=0.f;
    #pragma unroll 4
    for(int i=0;i<NC;i++){
      float w = W[i*NC + t];
      #pragma unroll
      for(int l=0;l<NK;l++) acc[l] += xin[i][l]*w;
    }
    bool last = (it==1);
    #pragma unroll
    for(int k=0;k<NK;k++){
      float v=0.f;
      #pragma unroll
      for(int l=0;l<NK;l++) v += A[k][l]*acc[l];
      xout[t][k] = last ? fmaxf(v,0.f) : v;
    }
    __syncthreads();
  }
  float ce[NK];
  #pragma unroll
  for(int k=0;k<NK;k++) ce[k]=0.f;
  #pragma unroll 4
  for(int i=0;i<NC;i++){
    float w = cwT[i*NC + t];
    #pragma unroll
    for(int k=0;k<NK;k++) ce[k] += xa[i][k]*w;
  }
  const float* sb = d_s  + (s*NB+b)*NK;
  const float* S2 = d_S2 + (s*NB+b)*64;
  float mp=0.f, vp=0.f;
  #pragma unroll
  for(int k=0;k<NK;k++) mp += ce[k]*sb[k];
  #pragma unroll
  for(int k=0;k<NK;k++)
    #pragma unroll
    for(int l=0;l<NK;l++) vp += ce[k]*ce[l]*S2[k*8+l];
  d_mpart[(s*NB+b)*NC + t] = mp;
  d_vpart[(s*NB+b)*NC + t] = vp;
  float* cep = d_ce + ((size_t)(s*NB+b)*NC + t)*NK;
  #pragma unroll
  for(int k=0;k<NK;k++) cep[k] = ce[k];
}

// ---------------- kG: fold BN stats into alpha/beta ----------------
__global__ void kG(const float* t2r_g, const float* t2r_b,
                   const float* r2t_g, const float* r2t_b){
  int s = blockIdx.x, t = threadIdx.x;
  const float* gg = s ? r2t_g : t2r_g;
  const float* bb = s ? r2t_b : t2r_b;
  float ms=0.f, vs=0.f;
  for(int b=0;b<NB;b++){ ms += d_mpart[(s*NB+b)*NC+t]; vs += d_vpart[(s*NB+b)*NC+t]; }
  float mean = ms * (1.f/65536.f);
  float ey2  = vs * (1.f/65536.f);
  float var  = ey2 - mean*mean;
  float al = gg[t]*rsqrtf(var + 1e-5f);
  d_alpha[s*NC+t] = al;
  d_beta [s*NC+t] = bb[t] - al*mean;
}

// ---------------- kH: out = gate*x + relu(alpha*((ce.ag)/g) + beta) ----------------
__global__ void __launch_bounds__(256) kH(const float* rgb, const float* tt, float* out){
  int chunk = blockIdx.x, b = blockIdx.y;
  int s = blockIdx.z >> 1, ch = blockIdx.z & 1;
  int t = threadIdx.x;
  __shared__ float ces[128][NK];
  __shared__ float al[128], be[128];
  int n0 = chunk*256;
  const float* agp = d_ag + (size_t)(s*NB+b)*NK*NN;
  float av[NK];
  #pragma unroll
  for(int k=0;k<NK;k++) av[k] = agp[(size_t)k*NN + n0 + t];
  float g = d_gate[(s*NB+b)*NN + n0 + t];
  float invg = __frcp_rn(g);
  const float* cep = d_ce + ((size_t)(s*NB+b)*NC + ch*128)*NK;
  for(int i=t;i<128*NK;i+=256) ((float*)ces)[i] = cep[i];
  if(t<128){ al[t]=d_alpha[s*NC+ch*128+t]; be[t]=d_beta[s*NC+ch*128+t]; }
  __syncthreads();
  const float* xp = (s ? tt : rgb) + (size_t)b*NC*NN;
  float* op = out + (size_t)s*HALF_OUT + (size_t)b*NC*NN;
  #pragma unroll 4
  for(int cl=0; cl<128; cl++){
    int c = ch*128 + cl;
    float xv = xp[(size_t)c*NN + n0 + t];
    float p = 0.f;
    #pragma unroll
    for(int k=0;k<NK;k++) p += ces[cl][k]*av[k];
    op[(size_t)c*NN + n0 + t] = g*xv + fmaxf(al[cl]*(p*invg) + be[cl], 0.f);
  }
}

// ---------------- launch ----------------
extern "C" void kernel_launch(void* const* d_in, const int* in_sizes, int n_in,
                              void* d_out, int out_size){
  (void)in_sizes; (void)n_in; (void)out_size;
  const float* rgb    = (const float*)d_in[0];
  const float* tt     = (const float*)d_in[1];
  const float* edger  = (const float*)d_in[2];
  const float* edget  = (const float*)d_in[3];
  const float* pred_w = (const float*)d_in[4];
  const float* pred_b = (const float*)d_in[5];
  const float* rgb_anchor=(const float*)d_in[6];
  const float* rgb_sigma =(const float*)d_in[7];
  const float* t_anchor  =(const float*)d_in[8];
  const float* t_sigma   =(const float*)d_in[9];
  const float* rgb_c1_w=(const float*)d_in[10]; const float* rgb_c1_g=(const float*)d_in[11]; const float* rgb_c1_b=(const float*)d_in[12];
  const float* rgb_c2_w=(const float*)d_in[13]; const float* rgb_c2_g=(const float*)d_in[14]; const float* rgb_c2_b=(const float*)d_in[15];
  const float* t_c1_w  =(const float*)d_in[16]; const float* t_c1_g  =(const float*)d_in[17]; const float* t_c1_b  =(const float*)d_in[18];
  const float* t_c2_w  =(const float*)d_in[19]; const float* t_c2_g  =(const float*)d_in[20]; const float* t_c2_b  =(const float*)d_in[21];
  const float* t2r_conv_w=(const float*)d_in[22]; const float* t2r_conv_g=(const float*)d_in[23]; const float* t2r_conv_b=(const float*)d_in[24];
  const float* r2t_conv_w=(const float*)d_in[25]; const float* r2t_conv_g=(const float*)d_in[26]; const float* r2t_conv_b=(const float*)d_in[27];
  const float* t2r_g1=(const float*)d_in[28]; const float* t2r_g2=(const float*)d_in[29];
  const float* r2t_g1=(const float*)d_in[30]; const float* r2t_g2=(const float*)d_in[31];
  float* out = (float*)d_out;

  kP <<<dim3(NK,2), NC>>>(rgb_anchor, rgb_sigma, t_anchor, t_sigma);
  kT <<<dim3(NC,2), NC>>>(t2r_conv_w, r2t_conv_w);
  kB <<<dim3(16,NB,2), 256>>>(rgb, tt, edger, edget, pred_w, pred_b);
  kC <<<dim3(32,NB,2), 256>>>(rgb, tt);
  kD <<<dim3(NB,2), NC>>>(rgb_anchor, rgb_sigma, t_anchor, t_sigma);
  kE <<<dim3(NC,4), 128>>>(rgb_c1_w,rgb_c1_g,rgb_c1_b, rgb_c2_w,rgb_c2_g,rgb_c2_b,
                           t_c1_w,t_c1_g,t_c1_b, t_c2_w,t_c2_g,t_c2_b);
  kF <<<dim3(NB,2), 256>>>(t2r_g1, t2r_g2, r2t_g1, r2t_g2);
  kG <<<2, NC>>>(t2r_conv_g, t2r_conv_b, r2t_conv_g, r2t_conv_b);
  kH <<<dim3(16,NB,4), 256>>>(rgb, tt, out);
}

// round 7
// speedup vs baseline: 1.2178x; 1.0272x over previous
#include <cuda_runtime.h>
#include <math.h>

#define NB 16
#define NC 256
#define NN 4096
#define NK 8
#define HALF_OUT (NB*NC*NN)

// ---------------- device scratch (no allocations allowed) ----------------
__device__ float  d_gate  [2*NB*NN];
__device__ float  d_ag    [2*NB*NK*NN];
__device__ float  d_s     [2*NB*NK];
__device__ float  d_S2    [2*NB*NK*NK];
__device__ float  d_wxp   [4*2*NB*NK*NC];     // per-nchunk partial wx
__device__ float  d_sS2p  [2*NB*8*44];        // per-chunk partial s/S2 from kB
__device__ float  d_gflat [2*NB*NK*NC];
__device__ float  d_y4    [4*NB*NC*NK];
__device__ float  d_ce    [2*NB*NC*NK];
__device__ float2 d_pre   [2*NK*NC];
__device__ float  d_ck    [2*NK];
__device__ float  d_cwT   [2*NC*NC];
__device__ float  d_mpart [2*NB*NC];
__device__ float  d_vpart [2*NB*NC];
__device__ float  d_alpha [2*NC];
__device__ float  d_beta  [2*NC];

// ---------------- helpers ----------------
__device__ __forceinline__ float sigmoidf_(float x){ return 1.f/(1.f+expf(-x)); }

__device__ __forceinline__ float warpSum(float v){
  #pragma unroll
  for(int o=16;o>0;o>>=1) v += __shfl_xor_sync(0xffffffffu, v, o);
  return v;
}
__device__ float blockSum(float v, float* scratch){
  int lane = threadIdx.x & 31, w = threadIdx.x >> 5;
  int nw = blockDim.x >> 5;
  v = warpSum(v);
  if(lane==0) scratch[w]=v;
  __syncthreads();
  float r = (threadIdx.x < nw) ? scratch[threadIdx.x] : 0.f;
  if(w==0) r = warpSum(r);
  if(threadIdx.x==0) scratch[0]=r;
  __syncthreads();
  r = scratch[0];
  __syncthreads();
  return r;
}

// ---------------- kP: per-side anchor coefficients ----------------
__global__ void kP(const float* rgb_anchor, const float* rgb_sigma,
                   const float* t_anchor,  const float* t_sigma){
  int s = blockIdx.y, k = blockIdx.x, t = threadIdx.x;
  const float* anc = s ? t_anchor : rgb_anchor;
  const float* sig = s ? t_sigma  : rgb_sigma;
  float sg  = sigmoidf_(sig[k*NC+t]);
  float is2 = 1.f/(sg*sg);
  float a   = anc[k*NC+t];
  d_pre[(s*NK+k)*NC+t] = make_float2(is2, 2.f*a*is2);
  __shared__ float sc[8];
  float ck = blockSum(a*a*is2, sc);
  if(t==0) d_ck[s*NK+k] = ck;
}

// ---------------- kT: transpose mutual-conv weights ----------------
__global__ void kT(const float* t2r_w, const float* r2t_w){
  int s = blockIdx.y, o = blockIdx.x, i = threadIdx.x;
  const float* w = s ? r2t_w : t2r_w;
  d_cwT[(size_t)s*NC*NC + i*NC + o] = w[o*NC + i];
}

// ---------------- kB: gate + q + softmax (2 px/thread, float4 coeff reads) ----------------
__global__ void __launch_bounds__(256) kB(const float* rgb, const float* tt,
      const float* edger, const float* edget, const float* pred_w, const float* pred_b){
  int chunk = blockIdx.x, b = blockIdx.y, s = blockIdx.z;
  int t = threadIdx.x;
  __shared__ float4 pre4[NK*128];     // (is2_c0, t2_c0, is2_c1, t2_c1) per (k, cpair)
  __shared__ float  pw[NC];
  __shared__ float  cks[NK];
  __shared__ float  part[44][8];
  pw[t] = pred_w[t];
  {
    const float4* src = (const float4*)(d_pre + (size_t)s*NK*NC);
    for(int i=t;i<NK*128;i+=256) pre4[i] = src[i];
  }
  if(t<NK) cks[t] = d_ck[s*NK+t];
  __syncthreads();
  int n0 = chunk*512;                 // 512 pixels per block, 2 per thread
  const float* ep = (s ? edget : edger) + (size_t)b*NC*NN + n0;
  const float* xp = (s ? tt    : rgb  ) + (size_t)b*NC*NN + n0;
  // ---- gate ----
  float ga0=0.f, ga1=0.f;
  {
    const float2* ep2 = (const float2*)ep;
    #pragma unroll 4
    for(int c=0;c<NC;c++){
      float2 ev = ep2[(size_t)c*(NN/2) + t];
      float w = pw[c];
      ga0 += w*ev.x; ga1 += w*ev.y;
    }
  }
  float pb = pred_b[0];
  float g0 = sigmoidf_(ga0+pb), g1 = sigmoidf_(ga1+pb);
  // ---- q distances ----
  float q0[NK], q1[NK];
  #pragma unroll
  for(int k=0;k<NK;k++){ q0[k]=cks[k]; q1[k]=cks[k]; }
  {
    const float2* xp2 = (const float2*)xp;
    #pragma unroll 2
    for(int cp=0;cp<128;cp++){
      float2 xa = xp2[(size_t)(2*cp  )*(NN/2) + t];
      float2 xb = xp2[(size_t)(2*cp+1)*(NN/2) + t];
      float xa0 = xa.x*g0, xa1 = xa.y*g1;
      float xb0 = xb.x*g0, xb1 = xb.y*g1;
      float xa0s=xa0*xa0, xa1s=xa1*xa1, xb0s=xb0*xb0, xb1s=xb1*xb1;
      #pragma unroll
      for(int k=0;k<NK;k++){
        float4 pc = pre4[k*128+cp];
        q0[k] += xa0s*pc.x - xa0*pc.y + xb0s*pc.z - xb0*pc.w;
        q1[k] += xa1s*pc.x - xa1*pc.y + xb1s*pc.z - xb1*pc.w;
      }
    }
  }
  // ---- softmax per pixel ----
  float a0[NK], a1[NK];
  {
    float mx0=-0.5f*q0[0], mx1=-0.5f*q1[0];
    #pragma unroll
    for(int k=1;k<NK;k++){ mx0=fmaxf(mx0,-0.5f*q0[k]); mx1=fmaxf(mx1,-0.5f*q1[k]); }
    float s0=0.f, s1=0.f;
    #pragma unroll
    for(int k=0;k<NK;k++){
      a0[k]=expf(-0.5f*q0[k]-mx0); s0+=a0[k];
      a1[k]=expf(-0.5f*q1[k]-mx1); s1+=a1[k];
    }
    float i0=1.f/s0, i1=1.f/s1;
    #pragma unroll
    for(int k=0;k<NK;k++){ a0[k]*=i0; a1[k]*=i1; }
  }
  // ---- write ag, gate ----
  {
    float* agp = d_ag + (size_t)(s*NB+b)*NK*NN + n0;
    #pragma unroll
    for(int k=0;k<NK;k++)
      ((float2*)(agp + (size_t)k*NN))[t] = make_float2(a0[k]*g0, a1[k]*g1);
    ((float2*)(d_gate + (size_t)(s*NB+b)*NN + n0))[t] = make_float2(g0, g1);
  }
  // ---- s/S2 partials ----
  int lane = t&31, w = t>>5;
  #pragma unroll
  for(int k=0;k<NK;k++){
    float v = warpSum(a0[k]+a1[k]);
    if(lane==0) part[k][w]=v;
  }
  int idx=8;
  #pragma unroll
  for(int k=0;k<NK;k++)
    #pragma unroll
    for(int l=k;l<NK;l++){
      float v = warpSum(a0[k]*a0[l] + a1[k]*a1[l]);
      if(lane==0) part[idx][w]=v;
      idx++;
    }
  __syncthreads();
  if(t<44){
    float sv=0.f;
    #pragma unroll
    for(int p=0;p<8;p++) sv += part[t][p];
    d_sS2p[((s*NB+b)*8+chunk)*44 + t] = sv;
  }
}

// ---------------- kC: partial wx (2 channels per thread per staged ag) ----------------
__global__ void __launch_bounds__(256) kC(const float* rgb, const float* tt){
  int bx = blockIdx.x;                // nch(4) x cgroup(4)
  int nch = bx>>2, cg = bx&3;
  int b = blockIdx.y, s = blockIdx.z;
  int t = threadIdx.x;
  int cl = t >> 3, nsub = t & 7;      // cl: 0..31, nsub: 0..7
  __shared__ float buf[8*1024];       // ags, then aliased as red
  float* ags = buf;                   // [8][1024]
  const float* agp = d_ag + (size_t)(s*NB+b)*NK*NN + nch*1024;
  for(int i=t;i<2048;i+=256){
    int k=i>>8, j=i&255;
    ((float4*)(ags + k*1024))[j] = ((const float4*)(agp + (size_t)k*NN))[j];
  }
  __syncthreads();
  int c0 = cg*64 + cl, c1 = c0 + 32;
  const float* xbase = (s ? tt : rgb) + (size_t)b*NC*NN + nch*1024;
  const float4* xp0 = (const float4*)(xbase + (size_t)c0*NN);
  const float4* xp1 = (const float4*)(xbase + (size_t)c1*NN);
  float acc0[NK], acc1[NK];
  #pragma unroll
  for(int k=0;k<NK;k++){ acc0[k]=0.f; acc1[k]=0.f; }
  #pragma unroll 4
  for(int i=0;i<32;i++){
    int j = nsub + i*8;
    float4 x0 = xp0[j];
    float4 x1 = xp1[j];
    #pragma unroll
    for(int k=0;k<NK;k++){
      float4 a4 = ((float4*)(ags + k*1024))[j];
      acc0[k] += a4.x*x0.x + a4.y*x0.y + a4.z*x0.z + a4.w*x0.w;
      acc1[k] += a4.x*x1.x + a4.y*x1.y + a4.z*x1.z + a4.w*x1.w;
    }
  }
  __syncthreads();                    // done reading ags; reuse buffer
  float (*red)[8][9] = (float(*)[8][9])buf;  // [64][8][9]
  #pragma unroll
  for(int k=0;k<NK;k++){ red[cl][nsub][k] = acc0[k]; red[cl+32][nsub][k] = acc1[k]; }
  __syncthreads();
  int cc = t>>3, k2 = t&7;
  float* wout = d_wxp + ((size_t)(nch*(2*NB) + s*NB+b)*NK + k2)*NC + cg*64;
  float s0 = 0.f, s1 = 0.f;
  #pragma unroll
  for(int p=0;p<8;p++){ s0 += red[cc][p][k2]; s1 += red[cc+32][p][k2]; }
  wout[cc]    = s0;
  wout[cc+32] = s1;
}

// ---------------- kD: reduce partials, nodes -> l2norms -> gflat ----------------
__global__ void kD(const float* rgb_anchor, const float* rgb_sigma,
                   const float* t_anchor,  const float* t_sigma){
  int b = blockIdx.x, s = blockIdx.y, t = threadIdx.x;
  __shared__ float v[NK][NC];
  __shared__ float sc[8];
  __shared__ float s_sh[NK];
  if(t<44){
    float sv=0.f;
    #pragma unroll
    for(int ch=0;ch<8;ch++) sv += d_sS2p[((s*NB+b)*8+ch)*44 + t];
    if(t<8){ d_s[(s*NB+b)*8 + t] = sv; s_sh[t] = sv; }
    else {
      int p=t-8, k=0;
      while(p >= NK-k){ p -= NK-k; k++; }
      int l = k+p;
      d_S2[(s*NB+b)*64 + k*8 + l] = sv;
      d_S2[(s*NB+b)*64 + l*8 + k] = sv;
    }
  }
  __syncthreads();
  const float* anc = s ? t_anchor : rgb_anchor;
  const float* sig = s ? t_sigma  : rgb_sigma;
  float nk[NK];
  for(int k=0;k<NK;k++){
    float wxv = 0.f;
    #pragma unroll
    for(int ch=0;ch<4;ch++)
      wxv += d_wxp[((size_t)(ch*(2*NB) + s*NB+b)*NK + k)*NC + t];
    float sv  = s_sh[k];
    float sg  = sigmoidf_(sig[k*NC+t]);
    float val = (wxv - sv*anc[k*NC+t]) / sg / (sv + 1e-9f);
    v[k][t] = val;
    float ss = blockSum(val*val, sc);
    nk[k] = fmaxf(sqrtf(ss), 1e-12f);
  }
  float gss = 0.f;
  for(int k=0;k<NK;k++){ float nv = v[k][t]/nk[k]; v[k][t]=nv; gss += nv*nv; }
  float G = blockSum(gss, sc);
  float gn = fmaxf(sqrtf(G), 1e-12f);
  float* gf = d_gflat + (size_t)(s*NB+b)*2048;
  for(int k=0;k<NK;k++) gf[k*NC+t] = v[k][t]/gn;
}

// ---------------- kE: 4 graph convs + BN(relu) over (B,K) ----------------
__global__ void __launch_bounds__(128) kE(
    const float* w0,const float* g0,const float* b0,
    const float* w1,const float* g1,const float* b1,
    const float* w2,const float* g2,const float* b2,
    const float* w3,const float* g3,const float* b3){
  int o = blockIdx.x, conv = blockIdx.y, t = threadIdx.x;
  const float *W, *gg, *bb;
  if(conv==0){W=w0;gg=g0;bb=b0;} else if(conv==1){W=w1;gg=g1;bb=b1;}
  else if(conv==2){W=w2;gg=g2;bb=b2;} else {W=w3;gg=g3;bb=b3;}
  int side = conv>>1;
  __shared__ float wr[NC];
  __shared__ float sc[8];
  wr[t] = W[o*NC + t]; wr[t+128] = W[o*NC + t + 128];
  __syncthreads();
  int b = t >> 3, k = t & 7;
  const float* gf = d_gflat + (size_t)(side*NB+b)*2048;
  float acc = 0.f;
  #pragma unroll 4
  for(int i=0;i<NC;i++) acc += wr[i]*gf[i*8+k];
  float su = blockSum(acc, sc);
  float sq = blockSum(acc*acc, sc);
  float mean = su*(1.f/128.f);
  float var  = sq*(1.f/128.f) - mean*mean;
  float y = gg[o]*(acc-mean)*rsqrtf(var+1e-5f) + bb[o];
  d_y4[((size_t)(conv*NB+b)*NC + o)*NK + k] = fmaxf(y, 0.f);
}

// ---------------- kF: mutual correlation + 2x cascade GCN + conv fold + BN stats ----------------
__global__ void __launch_bounds__(256) kF(
    const float* t2r_g1, const float* t2r_g2, const float* r2t_g1, const float* r2t_g2){
  int b = blockIdx.x, s = blockIdx.y, t = threadIdx.x;
  const float* W1  = s ? r2t_g1 : t2r_g1;
  const float* W2  = s ? r2t_g2 : t2r_g2;
  const float* cwT = d_cwT + (size_t)s*NC*NC;
  int c1 = s ? 0 : 2;
  __shared__ float e[NC][NK], r1[NC][NK], r2[NC][NK], xa[NC][NK], xb[NC][NK];
  __shared__ float A[NK][NK+1];
  {
    const float* gf = d_gflat + (size_t)(s*NB+b)*2048;
    const float* y1 = d_y4 + (size_t)(c1*NB+b)*NC*NK;
    const float* y2 = d_y4 + (size_t)((c1+1)*NB+b)*NC*NK;
    #pragma unroll
    for(int k=0;k<NK;k++){
      e [t][k] = gf[t*NK+k];
      r1[t][k] = y1[t*NK+k];
      r2[t][k] = y2[t*NK+k];
    }
  }
  __syncthreads();
  {
    int pair = t>>2, part = t&3;
    int k = pair>>3, l = pair&7;
    float acc=0.f;
    #pragma unroll 4
    for(int c=part;c<NC;c+=4) acc += e[c][k]*r1[c][l];
    acc += __shfl_down_sync(0xffffffffu, acc, 1);
    acc += __shfl_down_sync(0xffffffffu, acc, 2);
    if(part==0) A[k][l] = acc;
  }
  __syncthreads();
  if(t<NK){
    float mx=A[t][0];
    #pragma unroll
    for(int l=1;l<NK;l++) mx = fmaxf(mx, A[t][l]);
    float sm=0.f, ee[NK];
    #pragma unroll
    for(int l=0;l<NK;l++){ ee[l]=expf(A[t][l]-mx); sm+=ee[l]; }
    #pragma unroll
    for(int l=0;l<NK;l++) A[t][l] = ee[l]/sm;
  }
  __syncthreads();
  {
    float rr[NK];
    #pragma unroll
    for(int l=0;l<NK;l++) rr[l]=r2[t][l];
    #pragma unroll
    for(int k=0;k<NK;k++){
      float m=0.f;
      #pragma unroll
      for(int l=0;l<NK;l++) m += A[k][l]*rr[l];
      xa[t][k] = e[t][k] + m;
    }
  }
  __syncthreads();
  for(int it=0; it<2; it++){
    float (*xin)[NK]  = it ? xb : xa;
    float (*xout)[NK] = it ? xa : xb;
    const float* W = it ? W2 : W1;
    {
      int pair=t>>2, part=t&3, k=pair>>3, l=pair&7;
      float acc=0.f;
      #pragma unroll 4
      for(int c=part;c<NC;c+=4) acc += xin[c][k]*xin[c][l];
      acc += __shfl_down_sync(0xffffffffu, acc, 1);
      acc += __shfl_down_sync(0xffffffffu, acc, 2);
      if(part==0) A[k][l]=acc;
    }
    __syncthreads();
    if(t<NK){
      float mx=A[t][0];
      #pragma unroll
      for(int l=1;l<NK;l++) mx=fmaxf(mx,A[t][l]);
      float sm=0.f, ee[NK];
      #pragma unroll
      for(int l=0;l<NK;l++){ ee[l]=expf(A[t][l]-mx); sm+=ee[l]; }
      #pragma unroll
      for(int l=0;l<NK;l++) A[t][l]=ee[l]/sm;
    }
    __syncthreads();
    float acc[NK];
    #pragma unroll
    for(int l=0;l<NK;l++) acc[l]=0.f;
    #pragma unroll 4
    for(int i=0;i<NC;i++){
      float w = W[i*NC + t];
      #pragma unroll
      for(int l=0;l<NK;l++) acc[l] += xin[i][l]*w;
    }
    bool last = (it==1);
    #pragma unroll
    for(int k=0;k<NK;k++){
      float v=0.f;
      #pragma unroll
      for(int l=0;l<NK;l++) v += A[k][l]*acc[l];
      xout[t][k] = last ? fmaxf(v,0.f) : v;
    }
    __syncthreads();
  }
  float ce[NK];
  #pragma unroll
  for(int k=0;k<NK;k++) ce[k]=0.f;
  #pragma unroll 4
  for(int i=0;i<NC;i++){
    float w = cwT[i*NC + t];
    #pragma unroll
    for(int k=0;k<NK;k++) ce[k] += xa[i][k]*w;
  }
  const float* sb = d_s  + (s*NB+b)*NK;
  const float* S2 = d_S2 + (s*NB+b)*64;
  float mp=0.f, vp=0.f;
  #pragma unroll
  for(int k=0;k<NK;k++) mp += ce[k]*sb[k];
  #pragma unroll
  for(int k=0;k<NK;k++)
    #pragma unroll
    for(int l=0;l<NK;l++) vp += ce[k]*ce[l]*S2[k*8+l];
  d_mpart[(s*NB+b)*NC + t] = mp;
  d_vpart[(s*NB+b)*NC + t] = vp;
  float* cep = d_ce + ((size_t)(s*NB+b)*NC + t)*NK;
  #pragma unroll
  for(int k=0;k<NK;k++) cep[k] = ce[k];
}

// ---------------- kG: fold BN stats into alpha/beta ----------------
__global__ void kG(const float* t2r_g, const float* t2r_b,
                   const float* r2t_g, const float* r2t_b){
  int s = blockIdx.x, t = threadIdx.x;
  const float* gg = s ? r2t_g : t2r_g;
  const float* bb = s ? r2t_b : t2r_b;
  float ms=0.f, vs=0.f;
  for(int b=0;b<NB;b++){ ms += d_mpart[(s*NB+b)*NC+t]; vs += d_vpart[(s*NB+b)*NC+t]; }
  float mean = ms * (1.f/65536.f);
  float ey2  = vs * (1.f/65536.f);
  float var  = ey2 - mean*mean;
  float al = gg[t]*rsqrtf(var + 1e-5f);
  d_alpha[s*NC+t] = al;
  d_beta [s*NC+t] = bb[t] - al*mean;
}

// ---------------- kH: out = gate*x + relu(alpha*((ce.ag)/g) + beta), 4 px/thread ----------------
__global__ void __launch_bounds__(256) kH(const float* rgb, const float* tt, float* out){
  int chunk = blockIdx.x, b = blockIdx.y;
  int s = blockIdx.z >> 1, ch = blockIdx.z & 1;
  int t = threadIdx.x;
  __shared__ float4 ces4[128][2];     // ce rows for this channel half
  __shared__ float2 ab[128];
  int n0 = chunk*1024;                // 1024 px per block, 4 per thread
  const float* agp = d_ag + (size_t)(s*NB+b)*NK*NN + n0;
  float4 av[NK];
  #pragma unroll
  for(int k=0;k<NK;k++) av[k] = ((const float4*)(agp + (size_t)k*NN))[t];
  float4 gv = ((const float4*)(d_gate + (size_t)(s*NB+b)*NN + n0))[t];
  float4 ivg = make_float4(__frcp_rn(gv.x), __frcp_rn(gv.y), __frcp_rn(gv.z), __frcp_rn(gv.w));
  {
    const float4* cep = (const float4*)(d_ce + ((size_t)(s*NB+b)*NC + ch*128)*NK);
    for(int i=t;i<256;i+=256) ((float4*)ces4)[i] = cep[i];
    if(t<128) ab[t] = make_float2(d_alpha[s*NC+ch*128+t], d_beta[s*NC+ch*128+t]);
  }
  __syncthreads();
  const float* xp = (s ? tt : rgb) + (size_t)b*NC*NN + n0;
  float* op = out + (size_t)s*HALF_OUT + (size_t)b*NC*NN + n0;
  #pragma unroll 2
  for(int cl=0; cl<128; cl++){
    size_t coff = (size_t)(ch*128 + cl)*NN;
    float4 xv = ((const float4*)(xp + coff))[t];
    float4 ce0 = ces4[cl][0], ce1 = ces4[cl][1];
    float4 p;
    p.x = ce0.x*av[0].x + ce0.y*av[1].x + ce0.z*av[2].x + ce0.w*av[3].x
        + ce1.x*av[4].x + ce1.y*av[5].x + ce1.z*av[6].x + ce1.w*av[7].x;
    p.y = ce0.x*av[0].y + ce0.y*av[1].y + ce0.z*av[2].y + ce0.w*av[3].y
        + ce1.x*av[4].y + ce1.y*av[5].y + ce1.z*av[6].y + ce1.w*av[7].y;
    p.z = ce0.x*av[0].z + ce0.y*av[1].z + ce0.z*av[2].z + ce0.w*av[3].z
        + ce1.x*av[4].z + ce1.y*av[5].z + ce1.z*av[6].z + ce1.w*av[7].z;
    p.w = ce0.x*av[0].w + ce0.y*av[1].w + ce0.z*av[2].w + ce0.w*av[3].w
        + ce1.x*av[4].w + ce1.y*av[5].w + ce1.z*av[6].w + ce1.w*av[7].w;
    float2 abv = ab[cl];
    float4 o4;
    o4.x = gv.x*xv.x + fmaxf(abv.x*(p.x*ivg.x) + abv.y, 0.f);
    o4.y = gv.y*xv.y + fmaxf(abv.x*(p.y*ivg.y) + abv.y, 0.f);
    o4.z = gv.z*xv.z + fmaxf(abv.x*(p.z*ivg.z) + abv.y, 0.f);
    o4.w = gv.w*xv.w + fmaxf(abv.x*(p.w*ivg.w) + abv.y, 0.f);
    ((float4*)(op + coff))[t] = o4;
  }
}

// ---------------- launch ----------------
extern "C" void kernel_launch(void* const* d_in, const int* in_sizes, int n_in,
                              void* d_out, int out_size){
  (void)in_sizes; (void)n_in; (void)out_size;
  const float* rgb    = (const float*)d_in[0];
  const float* tt     = (const float*)d_in[1];
  const float* edger  = (const float*)d_in[2];
  const float* edget  = (const float*)d_in[3];
  const float* pred_w = (const float*)d_in[4];
  const float* pred_b = (const float*)d_in[5];
  const float* rgb_anchor=(const float*)d_in[6];
  const float* rgb_sigma =(const float*)d_in[7];
  const float* t_anchor  =(const float*)d_in[8];
  const float* t_sigma   =(const float*)d_in[9];
  const float* rgb_c1_w=(const float*)d_in[10]; const float* rgb_c1_g=(const float*)d_in[11]; const float* rgb_c1_b=(const float*)d_in[12];
  const float* rgb_c2_w=(const float*)d_in[13]; const float* rgb_c2_g=(const float*)d_in[14]; const float* rgb_c2_b=(const float*)d_in[15];
  const float* t_c1_w  =(const float*)d_in[16]; const float* t_c1_g  =(const float*)d_in[17]; const float* t_c1_b  =(const float*)d_in[18];
  const float* t_c2_w  =(const float*)d_in[19]; const float* t_c2_g  =(const float*)d_in[20]; const float* t_c2_b  =(const float*)d_in[21];
  const float* t2r_conv_w=(const float*)d_in[22]; const float* t2r_conv_g=(const float*)d_in[23]; const float* t2r_conv_b=(const float*)d_in[24];
  const float* r2t_conv_w=(const float*)d_in[25]; const float* r2t_conv_g=(const float*)d_in[26]; const float* r2t_conv_b=(const float*)d_in[27];
  const float* t2r_g1=(const float*)d_in[28]; const float* t2r_g2=(const float*)d_in[29];
  const float* r2t_g1=(const float*)d_in[30]; const float* r2t_g2=(const float*)d_in[31];
  float* out = (float*)d_out;

  kP <<<dim3(NK,2), NC>>>(rgb_anchor, rgb_sigma, t_anchor, t_sigma);
  kT <<<dim3(NC,2), NC>>>(t2r_conv_w, r2t_conv_w);
  kB <<<dim3(8,NB,2), 256>>>(rgb, tt, edger, edget, pred_w, pred_b);
  kC <<<dim3(16,NB,2), 256>>>(rgb, tt);
  kD <<<dim3(NB,2), NC>>>(rgb_anchor, rgb_sigma, t_anchor, t_sigma);
  kE <<<dim3(NC,4), 128>>>(rgb_c1_w,rgb_c1_g,rgb_c1_b, rgb_c2_w,rgb_c2_g,rgb_c2_b,
                           t_c1_w,t_c1_g,t_c1_b, t_c2_w,t_c2_g,t_c2_b);
  kF <<<dim3(NB,2), 256>>>(t2r_g1, t2r_g2, r2t_g1, r2t_g2);
  kG <<<2, NC>>>(t2r_conv_g, t2r_conv_b, r2t_conv_g, r2t_conv_b);
  kH <<<dim3(4,NB,4), 256>>>(rgb, tt, out);
}

// round 8
// speedup vs baseline: 1.4699x; 1.2071x over previous
#include <cuda_runtime.h>
#include <math.h>

#define NB 16
#define NC 256
#define NN 4096
#define NK 8
#define HALF_OUT (NB*NC*NN)

typedef unsigned long long u64;

// ---------------- device scratch ----------------
__device__ float  d_gate  [2*NB*NN];
__device__ float  d_ag    [2*NB*NK*NN];
__device__ float  d_s     [2*NB*NK];
__device__ float  d_S2    [2*NB*NK*NK];
__device__ float  d_wxp   [8*2*NB*NK*NC];     // per-512px-chunk partial wx
__device__ float  d_sS2p  [2*NB*8*44];        // per-chunk partial s/S2
__device__ float  d_gflat [2*NB*NK*NC];
__device__ float  d_y4    [4*NB*NC*NK];
__device__ float  d_ce    [2*NB*NC*NK];
__device__ float2 d_pre   [2*NK*NC];
__device__ float  d_ck    [2*NK];
__device__ float  d_cwT   [2*NC*NC];
__device__ float  d_mpart [2*NB*NC];
__device__ float  d_vpart [2*NB*NC];

// ---------------- helpers ----------------
__device__ __forceinline__ float sigmoidf_(float x){ return 1.f/(1.f+expf(-x)); }

__device__ __forceinline__ u64 pack2(float x, float y){
  u64 r; asm("mov.b64 %0,{%1,%2};" : "=l"(r) : "f"(x), "f"(y)); return r;
}
__device__ __forceinline__ void unpack2(u64 v, float& x, float& y){
  asm("mov.b64 {%0,%1},%2;" : "=f"(x), "=f"(y) : "l"(v));
}
__device__ __forceinline__ u64 ffma2(u64 a, u64 b, u64 c){
  u64 d; asm("fma.rn.f32x2 %0,%1,%2,%3;" : "=l"(d) : "l"(a), "l"(b), "l"(c)); return d;
}

__device__ __forceinline__ float warpSum(float v){
  #pragma unroll
  for(int o=16;o>0;o>>=1) v += __shfl_xor_sync(0xffffffffu, v, o);
  return v;
}
__device__ float blockSum(float v, float* scratch){
  int lane = threadIdx.x & 31, w = threadIdx.x >> 5;
  int nw = blockDim.x >> 5;
  v = warpSum(v);
  if(lane==0) scratch[w]=v;
  __syncthreads();
  float r = (threadIdx.x < nw) ? scratch[threadIdx.x] : 0.f;
  if(w==0) r = warpSum(r);
  if(threadIdx.x==0) scratch[0]=r;
  __syncthreads();
  r = scratch[0];
  __syncthreads();
  return r;
}

// ---------------- kI: anchor coefficients + weight transpose (fused init) ----------------
__global__ void kI(const float* rgb_anchor, const float* rgb_sigma,
                   const float* t_anchor,  const float* t_sigma,
                   const float* t2r_w, const float* r2t_w){
  int bid = blockIdx.x, t = threadIdx.x;
  if(bid < 16){
    int s = bid>>3, k = bid&7;
    const float* anc = s ? t_anchor : rgb_anchor;
    const float* sig = s ? t_sigma  : rgb_sigma;
    float sg  = sigmoidf_(sig[k*NC+t]);
    float is2 = 1.f/(sg*sg);
    float a   = anc[k*NC+t];
    d_pre[(s*NK+k)*NC+t] = make_float2(is2, 2.f*a*is2);
    __shared__ float sc[8];
    float ck = blockSum(a*a*is2, sc);
    if(t==0) d_ck[s*NK+k] = ck;
  } else {
    int r = bid-16, s = r>>8, o = r&255;
    const float* w = s ? r2t_w : t2r_w;
    d_cwT[(size_t)s*NC*NC + t*NC + o] = w[o*NC + t];
  }
}

// ---------------- kBC: gate + q + softmax + wx partials (fused, f32x2-packed) ----------------
__global__ void __launch_bounds__(256) kBC(const float* rgb, const float* tt,
      const float* edger, const float* edget, const float* pred_w, const float* pred_b){
  int chunk = blockIdx.x, b = blockIdx.y, s = blockIdx.z;
  int t = threadIdx.x;
  __shared__ u64 agsp[4][512];                 // packed (k-pair) assign*gate, 16 KB
  __shared__ __align__(16) char ubuf[18432];   // predup (16K) then red (18.4K)
  __shared__ float pw[NC];
  __shared__ float cks[NK];
  __shared__ float part[44][8];
  ulonglong2 (*predup)[256] = (ulonglong2(*)[256])ubuf;
  float (*red)[8][9] = (float(*)[8][9])ubuf;

  pw[t] = pred_w[t];
  for(int idx=t; idx<4*NC; idx+=256){
    int kp = idx >> 8, c = idx & 255;
    float2 pa = d_pre[s*2048 + (2*kp  )*NC + c];
    float2 pb = d_pre[s*2048 + (2*kp+1)*NC + c];
    ulonglong2 v;
    v.x = pack2(pa.x, pb.x);        // (is2_k0, is2_k1)
    v.y = pack2(-pa.y, -pb.y);      // (-t2_k0, -t2_k1)
    predup[kp][c] = v;
  }
  if(t<NK) cks[t] = d_ck[s*NK+t];
  __syncthreads();

  int n0 = chunk*512;                           // 512 px per block, 2 per thread
  const float* ep = (s ? edget : edger) + (size_t)b*NC*NN + n0;
  const float* xp = (s ? tt    : rgb  ) + (size_t)b*NC*NN + n0;

  // ---- gate (packed across the 2 pixels) ----
  u64 gaA = pack2(0.f,0.f), gaB = pack2(0.f,0.f);
  {
    const float2* ep2 = (const float2*)ep;
    #pragma unroll 4
    for(int c=0;c<NC;c+=2){
      float2 e0 = ep2[(size_t)(c  )*(NN/2) + t];
      float2 e1 = ep2[(size_t)(c+1)*(NN/2) + t];
      gaA = ffma2(pack2(pw[c],pw[c]),     pack2(e0.x,e0.y), gaA);
      gaB = ffma2(pack2(pw[c+1],pw[c+1]), pack2(e1.x,e1.y), gaB);
    }
  }
  float ga0,ga1, gb0,gb1;
  unpack2(gaA,ga0,ga1); unpack2(gaB,gb0,gb1);
  float pb = pred_b[0];
  float g0 = sigmoidf_(ga0+gb0+pb), g1 = sigmoidf_(ga1+gb1+pb);

  // ---- q distances, packed across cluster pairs ----
  u64 qaS[4], qaL[4], qbS[4], qbL[4];
  #pragma unroll
  for(int kp=0;kp<4;kp++){
    qaS[kp]=pack2(cks[2*kp],cks[2*kp+1]); qbS[kp]=qaS[kp];
    qaL[kp]=pack2(0.f,0.f); qbL[kp]=pack2(0.f,0.f);
  }
  {
    const float2* xp2 = (const float2*)xp;
    #pragma unroll 4
    for(int c=0;c<NC;c++){
      float2 xv = xp2[(size_t)c*(NN/2)+t];
      float x0 = xv.x*g0, x1 = xv.y*g1;
      float x0s = x0*x0,  x1s = x1*x1;
      u64 X0 = pack2(x0,x0),   X1 = pack2(x1,x1);
      u64 X0s= pack2(x0s,x0s), X1s= pack2(x1s,x1s);
      #pragma unroll
      for(int kp=0;kp<4;kp++){
        ulonglong2 pd = predup[kp][c];
        qaS[kp] = ffma2(X0s, pd.x, qaS[kp]);
        qaL[kp] = ffma2(X0,  pd.y, qaL[kp]);
        qbS[kp] = ffma2(X1s, pd.x, qbS[kp]);
        qbL[kp] = ffma2(X1,  pd.y, qbL[kp]);
      }
    }
  }
  float q0[NK], q1[NK];
  #pragma unroll
  for(int kp=0;kp<4;kp++){
    float sA,sB,lA,lB;
    unpack2(qaS[kp],sA,sB); unpack2(qaL[kp],lA,lB);
    q0[2*kp]=sA+lA; q0[2*kp+1]=sB+lB;
    unpack2(qbS[kp],sA,sB); unpack2(qbL[kp],lA,lB);
    q1[2*kp]=sA+lA; q1[2*kp+1]=sB+lB;
  }

  // ---- softmax per pixel ----
  float a0[NK], a1[NK];
  {
    float mx0=-0.5f*q0[0], mx1=-0.5f*q1[0];
    #pragma unroll
    for(int k=1;k<NK;k++){ mx0=fmaxf(mx0,-0.5f*q0[k]); mx1=fmaxf(mx1,-0.5f*q1[k]); }
    float s0=0.f, s1=0.f;
    #pragma unroll
    for(int k=0;k<NK;k++){
      a0[k]=expf(-0.5f*q0[k]-mx0); s0+=a0[k];
      a1[k]=expf(-0.5f*q1[k]-mx1); s1+=a1[k];
    }
    float i0=1.f/s0, i1=1.f/s1;
    #pragma unroll
    for(int k=0;k<NK;k++){ a0[k]*=i0; a1[k]*=i1; }
  }
  // ---- write ag (global, k-major) + gate; stage agsp (smem, kp-packed, px-major) ----
  {
    float a0g[NK], a1g[NK];
    #pragma unroll
    for(int k=0;k<NK;k++){ a0g[k]=a0[k]*g0; a1g[k]=a1[k]*g1; }
    float* agp = d_ag + (size_t)(s*NB+b)*NK*NN + n0;
    #pragma unroll
    for(int k=0;k<NK;k++)
      ((float2*)(agp + (size_t)k*NN))[t] = make_float2(a0g[k], a1g[k]);
    ((float2*)(d_gate + (size_t)(s*NB+b)*NN + n0))[t] = make_float2(g0, g1);
    #pragma unroll
    for(int kp=0;kp<4;kp++){
      ulonglong2 v;
      v.x = pack2(a0g[2*kp], a0g[2*kp+1]);   // pixel 2t
      v.y = pack2(a1g[2*kp], a1g[2*kp+1]);   // pixel 2t+1
      ((ulonglong2*)agsp[kp])[t] = v;
    }
  }
  // ---- s/S2 partials ----
  {
    int lane = t&31, w = t>>5;
    #pragma unroll
    for(int k=0;k<NK;k++){
      float v = warpSum(a0[k]+a1[k]);
      if(lane==0) part[k][w]=v;
    }
    int idx=8;
    #pragma unroll
    for(int k=0;k<NK;k++)
      #pragma unroll
      for(int l=k;l<NK;l++){
        float v = warpSum(a0[k]*a0[l] + a1[k]*a1[l]);
        if(lane==0) part[idx][w]=v;
        idx++;
      }
  }
  __syncthreads();
  if(t<44){
    float sv=0.f;
    #pragma unroll
    for(int p=0;p<8;p++) sv += part[t][p];
    d_sS2p[((s*NB+b)*8+chunk)*44 + t] = sv;
  }

  // ================= phase 2: wx partials from L2-resident x =================
  int cl = t>>3, nsub = t&7;
  for(int cg=0; cg<4; cg++){
    int c0 = cg*64 + cl, c1 = c0 + 32;
    const float4* x0p = (const float4*)(xp + (size_t)c0*NN);
    const float4* x1p = (const float4*)(xp + (size_t)c1*NN);
    u64 acc0[4], acc1[4];
    #pragma unroll
    for(int kp=0;kp<4;kp++){ acc0[kp]=pack2(0.f,0.f); acc1[kp]=acc0[kp]; }
    #pragma unroll 4
    for(int i=0;i<16;i++){
      int j = nsub + i*8;
      float4 xv0 = x0p[j];
      float4 xv1 = x1p[j];
      u64 P0x=pack2(xv0.x,xv0.x), P0y=pack2(xv0.y,xv0.y), P0z=pack2(xv0.z,xv0.z), P0w=pack2(xv0.w,xv0.w);
      u64 P1x=pack2(xv1.x,xv1.x), P1y=pack2(xv1.y,xv1.y), P1z=pack2(xv1.z,xv1.z), P1w=pack2(xv1.w,xv1.w);
      #pragma unroll
      for(int kp=0;kp<4;kp++){
        ulonglong2 apA = ((ulonglong2*)agsp[kp])[2*j];     // px 4j, 4j+1
        ulonglong2 apB = ((ulonglong2*)agsp[kp])[2*j+1];   // px 4j+2, 4j+3
        acc0[kp] = ffma2(P0x, apA.x, acc0[kp]);
        acc0[kp] = ffma2(P0y, apA.y, acc0[kp]);
        acc0[kp] = ffma2(P0z, apB.x, acc0[kp]);
        acc0[kp] = ffma2(P0w, apB.y, acc0[kp]);
        acc1[kp] = ffma2(P1x, apA.x, acc1[kp]);
        acc1[kp] = ffma2(P1y, apA.y, acc1[kp]);
        acc1[kp] = ffma2(P1z, apB.x, acc1[kp]);
        acc1[kp] = ffma2(P1w, apB.y, acc1[kp]);
      }
    }
    __syncthreads();
    #pragma unroll
    for(int kp=0;kp<4;kp++){
      float r0,r1;
      unpack2(acc0[kp],r0,r1); red[cl][nsub][2*kp]=r0; red[cl][nsub][2*kp+1]=r1;
      unpack2(acc1[kp],r0,r1); red[cl+32][nsub][2*kp]=r0; red[cl+32][nsub][2*kp+1]=r1;
    }
    __syncthreads();
    int cc = t>>3, k2 = t&7;
    float s0 = 0.f, s1 = 0.f;
    #pragma unroll
    for(int p=0;p<8;p++){ s0 += red[cc][p][k2]; s1 += red[cc+32][p][k2]; }
    float* wout = d_wxp + ((size_t)(chunk*(2*NB) + s*NB+b)*NK + k2)*NC + cg*64;
    wout[cc]    = s0;
    wout[cc+32] = s1;
  }
}

// ---------------- kD: reduce partials, nodes -> l2norms -> gflat ----------------
__global__ void kD(const float* rgb_anchor, const float* rgb_sigma,
                   const float* t_anchor,  const float* t_sigma){
  int b = blockIdx.x, s = blockIdx.y, t = threadIdx.x;
  __shared__ float v[NK][NC];
  __shared__ float sc[8];
  __shared__ float s_sh[NK];
  if(t<44){
    float sv=0.f;
    #pragma unroll
    for(int ch=0;ch<8;ch++) sv += d_sS2p[((s*NB+b)*8+ch)*44 + t];
    if(t<8){ d_s[(s*NB+b)*8 + t] = sv; s_sh[t] = sv; }
    else {
      int p=t-8, k=0;
      while(p >= NK-k){ p -= NK-k; k++; }
      int l = k+p;
      d_S2[(s*NB+b)*64 + k*8 + l] = sv;
      d_S2[(s*NB+b)*64 + l*8 + k] = sv;
    }
  }
  __syncthreads();
  const float* anc = s ? t_anchor : rgb_anchor;
  const float* sig = s ? t_sigma  : rgb_sigma;
  float nk[NK];
  for(int k=0;k<NK;k++){
    float wxv = 0.f;
    #pragma unroll
    for(int ch=0;ch<8;ch++)
      wxv += d_wxp[((size_t)(ch*(2*NB) + s*NB+b)*NK + k)*NC + t];
    float sv  = s_sh[k];
    float sg  = sigmoidf_(sig[k*NC+t]);
    float val = (wxv - sv*anc[k*NC+t]) / sg / (sv + 1e-9f);
    v[k][t] = val;
    float ss = blockSum(val*val, sc);
    nk[k] = fmaxf(sqrtf(ss), 1e-12f);
  }
  float gss = 0.f;
  for(int k=0;k<NK;k++){ float nv = v[k][t]/nk[k]; v[k][t]=nv; gss += nv*nv; }
  float G = blockSum(gss, sc);
  float gn = fmaxf(sqrtf(G), 1e-12f);
  float* gf = d_gflat + (size_t)(s*NB+b)*2048;
  for(int k=0;k<NK;k++) gf[k*NC+t] = v[k][t]/gn;
}

// ---------------- kE: 4 graph convs + BN(relu) over (B,K) ----------------
__global__ void __launch_bounds__(128) kE(
    const float* w0,const float* g0,const float* b0,
    const float* w1,const float* g1,const float* b1,
    const float* w2,const float* g2,const float* b2,
    const float* w3,const float* g3,const float* b3){
  int o = blockIdx.x, conv = blockIdx.y, t = threadIdx.x;
  const float *W, *gg, *bb;
  if(conv==0){W=w0;gg=g0;bb=b0;} else if(conv==1){W=w1;gg=g1;bb=b1;}
  else if(conv==2){W=w2;gg=g2;bb=b2;} else {W=w3;gg=g3;bb=b3;}
  int side = conv>>1;
  __shared__ float wr[NC];
  __shared__ float sc[8];
  wr[t] = W[o*NC + t]; wr[t+128] = W[o*NC + t + 128];
  __syncthreads();
  int b = t >> 3, k = t & 7;
  const float* gf = d_gflat + (size_t)(side*NB+b)*2048;
  float acc = 0.f;
  #pragma unroll 4
  for(int i=0;i<NC;i++) acc += wr[i]*gf[i*8+k];
  float su = blockSum(acc, sc);
  float sq = blockSum(acc*acc, sc);
  float mean = su*(1.f/128.f);
  float var  = sq*(1.f/128.f) - mean*mean;
  float y = gg[o]*(acc-mean)*rsqrtf(var+1e-5f) + bb[o];
  d_y4[((size_t)(conv*NB+b)*NC + o)*NK + k] = fmaxf(y, 0.f);
}

// ---------------- kF: mutual correlation + 2x cascade GCN + conv fold + BN stats ----------------
__global__ void __launch_bounds__(256) kF(
    const float* t2r_g1, const float* t2r_g2, const float* r2t_g1, const float* r2t_g2){
  int b = blockIdx.x, s = blockIdx.y, t = threadIdx.x;
  const float* W1  = s ? r2t_g1 : t2r_g1;
  const float* W2  = s ? r2t_g2 : t2r_g2;
  const float* cwT = d_cwT + (size_t)s*NC*NC;
  int c1 = s ? 0 : 2;
  __shared__ float e[NC][NK], r1[NC][NK], r2[NC][NK], xa[NC][NK], xb[NC][NK];
  __shared__ float A[NK][NK+1];
  {
    const float* gf = d_gflat + (size_t)(s*NB+b)*2048;
    const float* y1 = d_y4 + (size_t)(c1*NB+b)*NC*NK;
    const float* y2 = d_y4 + (size_t)((c1+1)*NB+b)*NC*NK;
    #pragma unroll
    for(int k=0;k<NK;k++){
      e [t][k] = gf[t*NK+k];
      r1[t][k] = y1[t*NK+k];
      r2[t][k] = y2[t*NK+k];
    }
  }
  __syncthreads();
  {
    int pair = t>>2, part = t&3;
    int k = pair>>3, l = pair&7;
    float acc=0.f;
    #pragma unroll 4
    for(int c=part;c<NC;c+=4) acc += e[c][k]*r1[c][l];
    acc += __shfl_down_sync(0xffffffffu, acc, 1);
    acc += __shfl_down_sync(0xffffffffu, acc, 2);
    if(part==0) A[k][l] = acc;
  }
  __syncthreads();
  if(t<NK){
    float mx=A[t][0];
    #pragma unroll
    for(int l=1;l<NK;l++) mx = fmaxf(mx, A[t][l]);
    float sm=0.f, ee[NK];
    #pragma unroll
    for(int l=0;l<NK;l++){ ee[l]=expf(A[t][l]-mx); sm+=ee[l]; }
    #pragma unroll
    for(int l=0;l<NK;l++) A[t][l] = ee[l]/sm;
  }
  __syncthreads();
  {
    float rr[NK];
    #pragma unroll
    for(int l=0;l<NK;l++) rr[l]=r2[t][l];
    #pragma unroll
    for(int k=0;k<NK;k++){
      float m=0.f;
      #pragma unroll
      for(int l=0;l<NK;l++) m += A[k][l]*rr[l];
      xa[t][k] = e[t][k] + m;
    }
  }
  __syncthreads();
  for(int it=0; it<2; it++){
    float (*xin)[NK]  = it ? xb : xa;
    float (*xout)[NK] = it ? xa : xb;
    const float* W = it ? W2 : W1;
    {
      int pair=t>>2, part=t&3, k=pair>>3, l=pair&7;
      float acc=0.f;
      #pragma unroll 4
      for(int c=part;c<NC;c+=4) acc += xin[c][k]*xin[c][l];
      acc += __shfl_down_sync(0xffffffffu, acc, 1);
      acc += __shfl_down_sync(0xffffffffu, acc, 2);
      if(part==0) A[k][l]=acc;
    }
    __syncthreads();
    if(t<NK){
      float mx=A[t][0];
      #pragma unroll
      for(int l=1;l<NK;l++) mx=fmaxf(mx,A[t][l]);
      float sm=0.f, ee[NK];
      #pragma unroll
      for(int l=0;l<NK;l++){ ee[l]=expf(A[t][l]-mx); sm+=ee[l]; }
      #pragma unroll
      for(int l=0;l<NK;l++) A[t][l]=ee[l]/sm;
    }
    __syncthreads();
    float acc[NK];
    #pragma unroll
    for(int l=0;l<NK;l++) acc[l]=0.f;
    #pragma unroll 4
    for(int i=0;i<NC;i++){
      float w = W[i*NC + t];
      #pragma unroll
      for(int l=0;l<NK;l++) acc[l] += xin[i][l]*w;
    }
    bool last = (it==1);
    #pragma unroll
    for(int k=0;k<NK;k++){
      float v=0.f;
      #pragma unroll
      for(int l=0;l<NK;l++) v += A[k][l]*acc[l];
      xout[t][k] = last ? fmaxf(v,0.f) : v;
    }
    __syncthreads();
  }
  float ce[NK];
  #pragma unroll
  for(int k=0;k<NK;k++) ce[k]=0.f;
  #pragma unroll 4
  for(int i=0;i<NC;i++){
    float w = cwT[i*NC + t];
    #pragma unroll
    for(int k=0;k<NK;k++) ce[k] += xa[i][k]*w;
  }
  const float* sb = d_s  + (s*NB+b)*NK;
  const float* S2 = d_S2 + (s*NB+b)*64;
  float mp=0.f, vp=0.f;
  #pragma unroll
  for(int k=0;k<NK;k++) mp += ce[k]*sb[k];
  #pragma unroll
  for(int k=0;k<NK;k++)
    #pragma unroll
    for(int l=0;l<NK;l++) vp += ce[k]*ce[l]*S2[k*8+l];
  d_mpart[(s*NB+b)*NC + t] = mp;
  d_vpart[(s*NB+b)*NC + t] = vp;
  float* cep = d_ce + ((size_t)(s*NB+b)*NC + t)*NK;
  #pragma unroll
  for(int k=0;k<NK;k++) cep[k] = ce[k];
}

// ---------------- kH: BN-fold + out = gate*x + relu(alpha*((ce.ag)/g) + beta) ----------------
__global__ void __launch_bounds__(256) kH(const float* rgb, const float* tt, float* out,
      const float* t2r_g, const float* t2r_b, const float* r2t_g, const float* r2t_b){
  int chunk = blockIdx.x, b = blockIdx.y;
  int s = blockIdx.z >> 2, cq = blockIdx.z & 3;   // 64-channel quarter
  int t = threadIdx.x;
  __shared__ u64 cesd[64][NK];                    // ce duplicated as f32x2
  __shared__ float2 ab[64];                       // (alpha, beta)
  int n0 = chunk*1024;                            // 1024 px per block, 4 per thread
  // alpha/beta recompute (folds former kG)
  if(t<64){
    int c = cq*64 + t;
    float ms=0.f, vs=0.f;
    #pragma unroll
    for(int b2=0;b2<NB;b2++){
      ms += d_mpart[(s*NB+b2)*NC + c];
      vs += d_vpart[(s*NB+b2)*NC + c];
    }
    float mean = ms * (1.f/65536.f);
    float var  = vs * (1.f/65536.f) - mean*mean;
    float gg = s ? r2t_g[c] : t2r_g[c];
    float bv = s ? r2t_b[c] : t2r_b[c];
    float al = gg*rsqrtf(var + 1e-5f);
    ab[t] = make_float2(al, bv - al*mean);
  }
  for(int idx=t; idx<64*NK; idx+=256){
    int cl = idx>>3, k = idx&7;
    float cv = d_ce[((size_t)(s*NB+b)*NC + cq*64+cl)*NK + k];
    cesd[cl][k] = pack2(cv, cv);
  }
  const float* agp = d_ag + (size_t)(s*NB+b)*NK*NN + n0;
  u64 avlo[NK], avhi[NK];
  float4 gv;
  {
    #pragma unroll
    for(int k=0;k<NK;k++){
      float4 a4 = ((const float4*)(agp + (size_t)k*NN))[t];
      avlo[k] = pack2(a4.x, a4.y);
      avhi[k] = pack2(a4.z, a4.w);
    }
    gv = ((const float4*)(d_gate + (size_t)(s*NB+b)*NN + n0))[t];
  }
  float4 ivg = make_float4(__frcp_rn(gv.x), __frcp_rn(gv.y), __frcp_rn(gv.z), __frcp_rn(gv.w));
  __syncthreads();
  const float* xp = (s ? tt : rgb) + (size_t)b*NC*NN + n0;
  float* op = out + (size_t)s*HALF_OUT + (size_t)b*NC*NN + n0;
  #pragma unroll 2
  for(int cl=0; cl<64; cl++){
    size_t coff = (size_t)(cq*64 + cl)*NN;
    float4 xv = ((const float4*)(xp + coff))[t];
    u64 p01 = pack2(0.f,0.f), p23 = pack2(0.f,0.f);
    #pragma unroll
    for(int k=0;k<NK;k++){
      u64 cd = cesd[cl][k];
      p01 = ffma2(avlo[k], cd, p01);
      p23 = ffma2(avhi[k], cd, p23);
    }
    float px_,py_,pz_,pw_;
    unpack2(p01,px_,py_); unpack2(p23,pz_,pw_);
    float2 abv = ab[cl];
    float4 o4;
    o4.x = gv.x*xv.x + fmaxf(abv.x*(px_*ivg.x) + abv.y, 0.f);
    o4.y = gv.y*xv.y + fmaxf(abv.x*(py_*ivg.y) + abv.y, 0.f);
    o4.z = gv.z*xv.z + fmaxf(abv.x*(pz_*ivg.z) + abv.y, 0.f);
    o4.w = gv.w*xv.w + fmaxf(abv.x*(pw_*ivg.w) + abv.y, 0.f);
    ((float4*)(op + coff))[t] = o4;
  }
}

// ---------------- launch ----------------
extern "C" void kernel_launch(void* const* d_in, const int* in_sizes, int n_in,
                              void* d_out, int out_size){
  (void)in_sizes; (void)n_in; (void)out_size;
  const float* rgb    = (const float*)d_in[0];
  const float* tt     = (const float*)d_in[1];
  const float* edger  = (const float*)d_in[2];
  const float* edget  = (const float*)d_in[3];
  const float* pred_w = (const float*)d_in[4];
  const float* pred_b = (const float*)d_in[5];
  const float* rgb_anchor=(const float*)d_in[6];
  const float* rgb_sigma =(const float*)d_in[7];
  const float* t_anchor  =(const float*)d_in[8];
  const float* t_sigma   =(const float*)d_in[9];
  const float* rgb_c1_w=(const float*)d_in[10]; const float* rgb_c1_g=(const float*)d_in[11]; const float* rgb_c1_b=(const float*)d_in[12];
  const float* rgb_c2_w=(const float*)d_in[13]; const float* rgb_c2_g=(const float*)d_in[14]; const float* rgb_c2_b=(const float*)d_in[15];
  const float* t_c1_w  =(const float*)d_in[16]; const float* t_c1_g  =(const float*)d_in[17]; const float* t_c1_b  =(const float*)d_in[18];
  const float* t_c2_w  =(const float*)d_in[19]; const float* t_c2_g  =(const float*)d_in[20]; const float* t_c2_b  =(const float*)d_in[21];
  const float* t2r_conv_w=(const float*)d_in[22]; const float* t2r_conv_g=(const float*)d_in[23]; const float* t2r_conv_b=(const float*)d_in[24];
  const float* r2t_conv_w=(const float*)d_in[25]; const float* r2t_conv_g=(const float*)d_in[26]; const float* r2t_conv_b=(const float*)d_in[27];
  const float* t2r_g1=(const float*)d_in[28]; const float* t2r_g2=(const float*)d_in[29];
  const float* r2t_g1=(const float*)d_in[30]; const float* r2t_g2=(const float*)d_in[31];
  float* out = (float*)d_out;

  kI <<<528, NC>>>(rgb_anchor, rgb_sigma, t_anchor, t_sigma, t2r_conv_w, r2t_conv_w);
  kBC<<<dim3(8,NB,2), 256>>>(rgb, tt, edger, edget, pred_w, pred_b);
  kD <<<dim3(NB,2), NC>>>(rgb_anchor, rgb_sigma, t_anchor, t_sigma);
  kE <<<dim3(NC,4), 128>>>(rgb_c1_w,rgb_c1_g,rgb_c1_b, rgb_c2_w,rgb_c2_g,rgb_c2_b,
                           t_c1_w,t_c1_g,t_c1_b, t_c2_w,t_c2_g,t_c2_b);
  kF <<<dim3(NB,2), 256>>>(t2r_g1, t2r_g2, r2t_g1, r2t_g2);
  kH <<<dim3(4,NB,8), 256>>>(rgb, tt, out, t2r_conv_g, t2r_conv_b, r2t_conv_g, r2t_conv_b);
}